// round 1
// baseline (speedup 1.0000x reference)
#include <cuda_runtime.h>
#include <math.h>

#define S 4096
#define D 512
#define SD (S * D)

// Scratch (no allocations allowed): 72 MB projections + 4x64 MB score mats
__device__ float g_proj[9 * SD];
__device__ float g_Sl[(size_t)S * S];
__device__ float g_Sr[(size_t)S * S];
__device__ float g_Sg[(size_t)S * S];
__device__ float g_Sp[(size_t)S * S];

// ---------------------------------------------------------------------------
// Classic 128x128x8 register-tiled SGEMM. C[M,N] = A[M,K] * B  (row-major)
// BT=false: B is [K,N].  BT=true: B is [N,K], compute A*B^T.
// All of M,N divisible by 128, K divisible by 8 (true for every call here).
// Interleaved per-thread tile (stride-16) => conflict-free LDS in mainloop.
// ---------------------------------------------------------------------------
template <bool BT>
__global__ __launch_bounds__(256) void sgemm(const float* __restrict__ A,
                                             const float* __restrict__ B,
                                             float* __restrict__ C,
                                             int M, int N, int K) {
    __shared__ float As[8][128];
    __shared__ float Bs[8][128];

    const int tid = threadIdx.x;
    const int cRow = blockIdx.y;
    const int cCol = blockIdx.x;
    const int tr = tid >> 4;    // 0..15
    const int tc = tid & 15;    // 0..15

    // load mapping: 256 threads x float4 = 1024 floats = one 128x8 tile
    const int aRow = tid >> 1;          // 0..127
    const int aCol = (tid & 1) << 2;    // 0 or 4
    const int bRow = tid >> 5;          // 0..7   (NN path)
    const int bCol = (tid & 31) << 2;   // 0..124 (NN path)

    const float* Abase  = A + (size_t)cRow * 128 * K;
    const float* BbaseT = B + (size_t)cCol * 128 * K;  // BT path
    const float* BbaseN = B + cCol * 128;              // NN path

    float acc[8][8];
#pragma unroll
    for (int i = 0; i < 8; i++)
#pragma unroll
        for (int j = 0; j < 8; j++) acc[i][j] = 0.0f;

    for (int kk = 0; kk < K; kk += 8) {
        float4 a = *reinterpret_cast<const float4*>(Abase + (size_t)aRow * K + kk + aCol);
        As[aCol + 0][aRow] = a.x;
        As[aCol + 1][aRow] = a.y;
        As[aCol + 2][aRow] = a.z;
        As[aCol + 3][aRow] = a.w;
        if (BT) {
            float4 b = *reinterpret_cast<const float4*>(BbaseT + (size_t)aRow * K + kk + aCol);
            Bs[aCol + 0][aRow] = b.x;
            Bs[aCol + 1][aRow] = b.y;
            Bs[aCol + 2][aRow] = b.z;
            Bs[aCol + 3][aRow] = b.w;
        } else {
            float4 b = *reinterpret_cast<const float4*>(BbaseN + (size_t)(kk + bRow) * N + bCol);
            Bs[bRow][bCol + 0] = b.x;
            Bs[bRow][bCol + 1] = b.y;
            Bs[bRow][bCol + 2] = b.z;
            Bs[bRow][bCol + 3] = b.w;
        }
        __syncthreads();

#pragma unroll
        for (int k = 0; k < 8; k++) {
            float ra[8], rb[8];
#pragma unroll
            for (int i = 0; i < 8; i++) ra[i] = As[k][tr + 16 * i];
#pragma unroll
            for (int j = 0; j < 8; j++) rb[j] = Bs[k][tc + 16 * j];
#pragma unroll
            for (int i = 0; i < 8; i++)
#pragma unroll
                for (int j = 0; j < 8; j++) acc[i][j] = fmaf(ra[i], rb[j], acc[i][j]);
        }
        __syncthreads();
    }

#pragma unroll
    for (int i = 0; i < 8; i++) {
        float* Crow = C + (size_t)(cRow * 128 + tr + 16 * i) * N + cCol * 128;
#pragma unroll
        for (int j = 0; j < 8; j++) Crow[tc + 16 * j] = acc[i][j];
    }
}

// ---------------------------------------------------------------------------
// Block helpers (256 threads)
// ---------------------------------------------------------------------------
__device__ __forceinline__ float blockMax(float v, float* sh) {
    int t = threadIdx.x;
    sh[t] = v;
    __syncthreads();
    for (int o = 128; o > 0; o >>= 1) {
        if (t < o) sh[t] = fmaxf(sh[t], sh[t + o]);
        __syncthreads();
    }
    float r = sh[0];
    __syncthreads();
    return r;
}

__device__ __forceinline__ float blockSum(float v, float* sh) {
    int t = threadIdx.x;
    sh[t] = v;
    __syncthreads();
    for (int o = 128; o > 0; o >>= 1) {
        if (t < o) sh[t] += sh[t + o];
        __syncthreads();
    }
    float r = sh[0];
    __syncthreads();
    return r;
}

// inclusive prefix scan across 256 threads; also returns the total
__device__ __forceinline__ float blockScanIncl(float v, float* sh, float* total) {
    int t = threadIdx.x;
    sh[t] = v;
    __syncthreads();
    for (int o = 1; o < 256; o <<= 1) {
        float x = (t >= o) ? sh[t - o] : 0.0f;
        __syncthreads();
        sh[t] += x;
        __syncthreads();
    }
    float incl = sh[t];
    float tot = sh[255];
    __syncthreads();
    *total = tot;
    return incl;
}

// ---------------------------------------------------------------------------
// Fused per-row pipeline. One block (256 thr) per row i; each thread owns a
// contiguous chunk of 16 columns.
//   left : softmax over j<=i of Sl/norm, forward cumsum  -> lcdf (==1 for j>=i)
//   right: softmax over j>=i of Sr/norm, reverse cumsum  -> rcdf (==1 for j<=i)
//   score = (Sg + Sp*lcdf*rcdf)/norm ; softmax -> att_weight row
// ---------------------------------------------------------------------------
__global__ __launch_bounds__(256) void row_fused(float* __restrict__ Wout) {
    __shared__ float sh[256];
    const int i = blockIdx.x;
    const int t = threadIdx.x;
    const int j0 = t * 16;
    const float inv_norm = 0.04419417382415922f;  // 1/sqrt(512)

    const float* Sl = g_Sl + (size_t)i * S;
    const float* Sr = g_Sr + (size_t)i * S;
    const float* Sg = g_Sg + (size_t)i * S;
    const float* Sp = g_Sp + (size_t)i * S;

    float lcdf[16], rcdf[16];

    // ---------------- left boundary ----------------
    {
        float e[16];
        float m = -1e30f;
#pragma unroll
        for (int u4 = 0; u4 < 4; u4++) {
            float4 v = *reinterpret_cast<const float4*>(Sl + j0 + 4 * u4);
            e[4 * u4 + 0] = v.x; e[4 * u4 + 1] = v.y;
            e[4 * u4 + 2] = v.z; e[4 * u4 + 3] = v.w;
        }
#pragma unroll
        for (int u = 0; u < 16; u++) {
            int j = j0 + u;
            float s = (j <= i) ? e[u] * inv_norm : -1e30f;
            e[u] = s;
            m = fmaxf(m, s);
        }
        m = blockMax(m, sh);
        float lsum = 0.0f;
#pragma unroll
        for (int u = 0; u < 16; u++) {
            int j = j0 + u;
            float ev = (j <= i) ? __expf(e[u] - m) : 0.0f;
            e[u] = ev;
            lsum += ev;
        }
        float tot;
        float incl = blockScanIncl(lsum, sh, &tot);
        float off = incl - lsum;  // exclusive prefix of thread chunk
        float inv = 1.0f / tot;
        float c = 0.0f;
#pragma unroll
        for (int u = 0; u < 16; u++) {
            c += e[u];
            lcdf[u] = (c + off) * inv;
        }
    }

    // ---------------- right boundary ----------------
    {
        float e[16];
        float m = -1e30f;
#pragma unroll
        for (int u4 = 0; u4 < 4; u4++) {
            float4 v = *reinterpret_cast<const float4*>(Sr + j0 + 4 * u4);
            e[4 * u4 + 0] = v.x; e[4 * u4 + 1] = v.y;
            e[4 * u4 + 2] = v.z; e[4 * u4 + 3] = v.w;
        }
#pragma unroll
        for (int u = 0; u < 16; u++) {
            int j = j0 + u;
            float s = (j >= i) ? e[u] * inv_norm : -1e30f;
            e[u] = s;
            m = fmaxf(m, s);
        }
        m = blockMax(m, sh);
        float rsum = 0.0f;
#pragma unroll
        for (int u = 0; u < 16; u++) {
            int j = j0 + u;
            float ev = (j >= i) ? __expf(e[u] - m) : 0.0f;
            e[u] = ev;
            rsum += ev;
        }
        float tot;
        float incl = blockScanIncl(rsum, sh, &tot);
        float suff = tot - incl;  // exclusive suffix of thread chunk
        float inv = 1.0f / tot;
        float c = 0.0f;
#pragma unroll
        for (int u = 15; u >= 0; u--) {
            c += e[u];
            rcdf[u] = (c + suff) * inv;
        }
    }

    // ---------------- combined score + final softmax ----------------
    {
        float w[16], p[16];
#pragma unroll
        for (int u4 = 0; u4 < 4; u4++) {
            float4 vg = *reinterpret_cast<const float4*>(Sg + j0 + 4 * u4);
            float4 vp = *reinterpret_cast<const float4*>(Sp + j0 + 4 * u4);
            w[4 * u4 + 0] = vg.x; w[4 * u4 + 1] = vg.y;
            w[4 * u4 + 2] = vg.z; w[4 * u4 + 3] = vg.w;
            p[4 * u4 + 0] = vp.x; p[4 * u4 + 1] = vp.y;
            p[4 * u4 + 2] = vp.z; p[4 * u4 + 3] = vp.w;
        }
        float m = -1e30f;
#pragma unroll
        for (int u = 0; u < 16; u++) {
            float sc = (w[u] + p[u] * lcdf[u] * rcdf[u]) * inv_norm;
            w[u] = sc;
            m = fmaxf(m, sc);
        }
        m = blockMax(m, sh);
        float lsum = 0.0f;
#pragma unroll
        for (int u = 0; u < 16; u++) {
            float ev = __expf(w[u] - m);
            w[u] = ev;
            lsum += ev;
        }
        float tot = blockSum(lsum, sh);
        float inv = 1.0f / tot;
        float* Wrow = Wout + (size_t)i * S + j0;
#pragma unroll
        for (int u4 = 0; u4 < 4; u4++) {
            float4 o;
            o.x = w[4 * u4 + 0] * inv;
            o.y = w[4 * u4 + 1] * inv;
            o.z = w[4 * u4 + 2] * inv;
            o.w = w[4 * u4 + 3] * inv;
            *reinterpret_cast<float4*>(Wrow + 4 * u4) = o;
        }
    }
}

// ---------------------------------------------------------------------------
// Launch:   inputs: x, w_ql, w_kl, w_qr, w_kr, w_qg, w_kg, w_qloc, w_kloc, w_v
// Output layout: [att_output (S*D) | att_weight (S*S)]
// ---------------------------------------------------------------------------
extern "C" void kernel_launch(void* const* d_in, const int* in_sizes, int n_in,
                              void* d_out, int out_size) {
    const float* x = (const float*)d_in[0];
    const float* w[9];
    for (int i = 0; i < 9; i++) w[i] = (const float*)d_in[1 + i];

    float* out = (float*)d_out;
    float* Wout = out + SD;  // att_weight region

    float *proj, *sl, *sr, *sg, *sp;
    cudaGetSymbolAddress((void**)&proj, g_proj);
    cudaGetSymbolAddress((void**)&sl, g_Sl);
    cudaGetSymbolAddress((void**)&sr, g_Sr);
    cudaGetSymbolAddress((void**)&sg, g_Sg);
    cudaGetSymbolAddress((void**)&sp, g_Sp);

    // 1) projections: proj[i] = x @ w[i]   (ql,kl,qr,kr,qg,kg,qloc,kloc,v)
    dim3 gProj(D / 128, S / 128);
    for (int i = 0; i < 9; i++)
        sgemm<false><<<gProj, 256>>>(x, w[i], proj + (size_t)i * SD, S, D, D);

    // 2) raw score matrices: Q @ K^T
    dim3 gS(S / 128, S / 128);
    sgemm<true><<<gS, 256>>>(proj + 0 * (size_t)SD, proj + 1 * (size_t)SD, sl, S, S, D);
    sgemm<true><<<gS, 256>>>(proj + 2 * (size_t)SD, proj + 3 * (size_t)SD, sr, S, S, D);
    sgemm<true><<<gS, 256>>>(proj + 4 * (size_t)SD, proj + 5 * (size_t)SD, sg, S, S, D);
    sgemm<true><<<gS, 256>>>(proj + 6 * (size_t)SD, proj + 7 * (size_t)SD, sp, S, S, D);

    // 3) fused boundary softmaxes + cumsums + combine + final softmax
    row_fused<<<S, 256>>>(Wout);

    // 4) att_output = att_weight @ v
    dim3 gO(D / 128, S / 128);
    sgemm<false><<<gO, 256>>>(Wout, proj + 8 * (size_t)SD, out, S, D, S);
}

// round 3
// speedup vs baseline: 2.6725x; 2.6725x over previous
#include <cuda_runtime.h>
#include <cuda_bf16.h>
#include <cstdint>

#define S 4096
#define D 512
#define SD (S * D)
#define DD (D * D)

// ---------------------------------------------------------------------------
// Scratch (__device__ globals; no allocations allowed)
// ---------------------------------------------------------------------------
__device__ __nv_bfloat16 g_Xh[SD], g_Xl[SD];
__device__ __nv_bfloat16 g_WTh[9 * DD], g_WTl[9 * DD];
__device__ __nv_bfloat16 g_Ph[8 * (size_t)SD], g_Pl[8 * (size_t)SD];
__device__ __nv_bfloat16 g_VTh[SD], g_VTl[SD];
__device__ float g_S4[4 * (size_t)S * S];
__device__ __nv_bfloat16 g_Wh[(size_t)S * S], g_Wl[(size_t)S * S];

// ---------------------------------------------------------------------------
// PTX helpers (all baseline PTX, legal on compute_103)
// ---------------------------------------------------------------------------
__device__ __forceinline__ uint32_t smem_u32(const void* p) {
    uint32_t a;
    asm("{ .reg .u64 t; cvta.to.shared.u64 t, %1; cvt.u32.u64 %0, t; }"
        : "=r"(a) : "l"(p));
    return a;
}

#define CP_ASYNC16(dst, src) \
    asm volatile("cp.async.cg.shared.global [%0], [%1], 16;" :: "r"(dst), "l"(src))
#define CP_COMMIT() asm volatile("cp.async.commit_group;" ::: "memory")
#define CP_WAIT0()  asm volatile("cp.async.wait_group 0;" ::: "memory")

__device__ __forceinline__ void ldsm4(uint32_t* r, uint32_t addr) {
    asm volatile("ldmatrix.sync.aligned.m8n8.x4.shared.b16 {%0,%1,%2,%3}, [%4];"
                 : "=r"(r[0]), "=r"(r[1]), "=r"(r[2]), "=r"(r[3]) : "r"(addr));
}

__device__ __forceinline__ void mma16816(float* c, const uint32_t* a,
                                         const uint32_t* b) {
    asm volatile(
        "mma.sync.aligned.m16n8k16.row.col.f32.bf16.bf16.f32 "
        "{%0,%1,%2,%3}, {%4,%5,%6,%7}, {%8,%9}, {%0,%1,%2,%3};"
        : "+f"(c[0]), "+f"(c[1]), "+f"(c[2]), "+f"(c[3])
        : "r"(a[0]), "r"(a[1]), "r"(a[2]), "r"(a[3]), "r"(b[0]), "r"(b[1]));
}

// swizzled offset within an 8KB tile: 128 rows x 64B (4 x 16B slots)
__device__ __forceinline__ uint32_t swz(int r, int c16) {
    return (uint32_t)(r * 64 + ((c16 ^ ((r >> 1) & 3)) << 4));
}

// ---------------------------------------------------------------------------
// HMMA bf16x3 GEMM:  C[M,N] = Ah@Bh^T + Ah@Bl^T + Al@Bh^T   (A,B K-major)
// CTA 128x128, 8 warps (warp tile 64x32), K-chunk 32, 2-stage cp.async.
// MODE 0: fp32 C row-major.  MODE 1: bf16 hi/lo row-major.
// MODE 2: bf16 hi/lo transposed (CT[n*Mtot+m]).
// ---------------------------------------------------------------------------
enum { MODE_F32 = 0, MODE_SPLIT = 1, MODE_SPLIT_T = 2 };

constexpr int SMEM_SZ = 2 * 4 * 8192;  // 2 stages x 4 tiles x 8KB = 64KB

template <int MODE>
__global__ void __launch_bounds__(256, 1)
gemm_hmma(const __nv_bfloat16* __restrict__ Ah, const __nv_bfloat16* __restrict__ Al,
          const __nv_bfloat16* __restrict__ Bh, const __nv_bfloat16* __restrict__ Bl,
          float* __restrict__ C, __nv_bfloat16* __restrict__ Ch,
          __nv_bfloat16* __restrict__ Cl, int Mtot, int Ntot, int K) {
    extern __shared__ char sm[];
    const uint32_t sbase = smem_u32(sm);
    const int t = threadIdx.x, lid = t & 31, wid = t >> 5;
    const int wm = wid & 1, wn = wid >> 1;
    const int m0 = blockIdx.y * 128, n0 = blockIdx.x * 128;

    float acc[4][4][4];
#pragma unroll
    for (int i = 0; i < 4; i++)
#pragma unroll
        for (int j = 0; j < 4; j++)
#pragma unroll
            for (int k = 0; k < 4; k++) acc[i][j][k] = 0.0f;

    const __nv_bfloat16* G[4] = {Ah + (size_t)m0 * K, Al + (size_t)m0 * K,
                                 Bh + (size_t)n0 * K, Bl + (size_t)n0 * K};
    const int lr = t >> 1;            // load row 0..127
    const int lc0 = (t & 1) * 2;      // first 16B slot
    const int NCH = K >> 5;

    // ldmatrix lane coords
    const int a_row = lid & 15;
    const int a_chi = lid >> 4;
    const int b_row = (lid & 7) + ((lid >> 4) << 3);
    const int b_chi = (lid >> 3) & 1;

#define CP_CHUNK(ch, st)                                                       \
    do {                                                                       \
        int kk_ = (ch) * 32;                                                   \
        _Pragma("unroll")                                                      \
        for (int tile_ = 0; tile_ < 4; tile_++) {                              \
            const char* gs_ = (const char*)(G[tile_] + (size_t)lr * K + kk_);  \
            _Pragma("unroll")                                                  \
            for (int i_ = 0; i_ < 2; i_++) {                                   \
                int c16_ = lc0 + i_;                                           \
                uint32_t d_ = sbase + (st) * 32768 + tile_ * 8192 + swz(lr, c16_); \
                CP_ASYNC16(d_, gs_ + c16_ * 16);                               \
            }                                                                  \
        }                                                                      \
        CP_COMMIT();                                                           \
    } while (0)

    CP_CHUNK(0, 0);

    for (int c = 0; c < NCH; c++) {
        const int st = c & 1;
        CP_WAIT0();
        __syncthreads();
        if (c + 1 < NCH) CP_CHUNK(c + 1, st ^ 1);

        const uint32_t base = sbase + st * 32768;
#pragma unroll
        for (int q = 0; q < 2; q++) {
            uint32_t ahf[4][4], alf[4][4], bhf[4][2], blf[4][2];
#pragma unroll
            for (int am = 0; am < 4; am++) {
                int r = wm * 64 + am * 16 + a_row;
                uint32_t off = swz(r, q * 2 + a_chi);
                ldsm4(ahf[am], base + 0 * 8192 + off);
                ldsm4(alf[am], base + 1 * 8192 + off);
            }
#pragma unroll
            for (int g2 = 0; g2 < 2; g2++) {
                int r = wn * 32 + g2 * 16 + b_row;
                uint32_t off = swz(r, q * 2 + b_chi);
                uint32_t rh[4], rl[4];
                ldsm4(rh, base + 2 * 8192 + off);
                ldsm4(rl, base + 3 * 8192 + off);
                bhf[2 * g2 + 0][0] = rh[0]; bhf[2 * g2 + 0][1] = rh[1];
                bhf[2 * g2 + 1][0] = rh[2]; bhf[2 * g2 + 1][1] = rh[3];
                blf[2 * g2 + 0][0] = rl[0]; blf[2 * g2 + 0][1] = rl[1];
                blf[2 * g2 + 1][0] = rl[2]; blf[2 * g2 + 1][1] = rl[3];
            }
#pragma unroll
            for (int am = 0; am < 4; am++)
#pragma unroll
                for (int an = 0; an < 4; an++) {
                    mma16816(acc[am][an], ahf[am], bhf[an]);
                    mma16816(acc[am][an], ahf[am], blf[an]);
                    mma16816(acc[am][an], alf[am], bhf[an]);
                }
        }
    }

    // epilogue
    const int t4 = lid >> 2;        // 0..7
    const int n2 = (lid & 3) * 2;
#pragma unroll
    for (int am = 0; am < 4; am++) {
#pragma unroll
        for (int an = 0; an < 4; an++) {
            int m_lo = m0 + wm * 64 + am * 16 + t4;
            int n = n0 + wn * 32 + an * 8 + n2;
            float* a4 = acc[am][an];
            if (MODE == MODE_F32) {
                *(float2*)(C + (size_t)m_lo * Ntot + n) = make_float2(a4[0], a4[1]);
                *(float2*)(C + (size_t)(m_lo + 8) * Ntot + n) = make_float2(a4[2], a4[3]);
            } else if (MODE == MODE_SPLIT) {
#pragma unroll
                for (int h2 = 0; h2 < 2; h2++) {
                    int m = m_lo + 8 * h2;
                    float v0 = a4[2 * h2], v1 = a4[2 * h2 + 1];
                    __nv_bfloat16 h0 = __float2bfloat16(v0);
                    __nv_bfloat16 h1 = __float2bfloat16(v1);
                    __nv_bfloat162 hh; hh.x = h0; hh.y = h1;
                    __nv_bfloat162 ll;
                    ll.x = __float2bfloat16(v0 - __bfloat162float(h0));
                    ll.y = __float2bfloat16(v1 - __bfloat162float(h1));
                    *(__nv_bfloat162*)(Ch + (size_t)m * Ntot + n) = hh;
                    *(__nv_bfloat162*)(Cl + (size_t)m * Ntot + n) = ll;
                }
            } else {  // MODE_SPLIT_T
#pragma unroll
                for (int h2 = 0; h2 < 2; h2++) {
                    int m = m_lo + 8 * h2;
#pragma unroll
                    for (int e = 0; e < 2; e++) {
                        float v = a4[2 * h2 + e];
                        __nv_bfloat16 h = __float2bfloat16(v);
                        Ch[(size_t)(n + e) * Mtot + m] = h;
                        Cl[(size_t)(n + e) * Mtot + m] =
                            __float2bfloat16(v - __bfloat162float(h));
                    }
                }
            }
        }
    }
#undef CP_CHUNK
}

// ---------------------------------------------------------------------------
// split / transpose-split kernels
// ---------------------------------------------------------------------------
__global__ void split_x(const float* __restrict__ x, __nv_bfloat16* __restrict__ xh,
                        __nv_bfloat16* __restrict__ xl) {
    int i = blockIdx.x * 256 + threadIdx.x;
    float v = x[i];
    __nv_bfloat16 h = __float2bfloat16(v);
    xh[i] = h;
    xl[i] = __float2bfloat16(v - __bfloat162float(h));
}

__global__ void splitT_w(const float* __restrict__ W, __nv_bfloat16* __restrict__ Th,
                         __nv_bfloat16* __restrict__ Tl) {
    int i = blockIdx.x * 256 + threadIdx.x;  // i = n*512 + k
    int n = i >> 9, k = i & 511;
    float v = W[k * D + n];
    __nv_bfloat16 h = __float2bfloat16(v);
    Th[i] = h;
    Tl[i] = __float2bfloat16(v - __bfloat162float(h));
}

// ---------------------------------------------------------------------------
// Block helpers (256 threads)
// ---------------------------------------------------------------------------
__device__ __forceinline__ float blockMax(float v, float* sh) {
    int t = threadIdx.x;
    sh[t] = v;
    __syncthreads();
    for (int o = 128; o > 0; o >>= 1) {
        if (t < o) sh[t] = fmaxf(sh[t], sh[t + o]);
        __syncthreads();
    }
    float r = sh[0];
    __syncthreads();
    return r;
}

__device__ __forceinline__ float blockSum(float v, float* sh) {
    int t = threadIdx.x;
    sh[t] = v;
    __syncthreads();
    for (int o = 128; o > 0; o >>= 1) {
        if (t < o) sh[t] += sh[t + o];
        __syncthreads();
    }
    float r = sh[0];
    __syncthreads();
    return r;
}

__device__ __forceinline__ float blockScanIncl(float v, float* sh, float* total) {
    int t = threadIdx.x;
    sh[t] = v;
    __syncthreads();
    for (int o = 1; o < 256; o <<= 1) {
        float x = (t >= o) ? sh[t - o] : 0.0f;
        __syncthreads();
        sh[t] += x;
        __syncthreads();
    }
    float incl = sh[t];
    float tot = sh[255];
    __syncthreads();
    *total = tot;
    return incl;
}

// ---------------------------------------------------------------------------
// Fused per-row pipeline (also emits bf16 hi/lo of att_weight for final GEMM)
// ---------------------------------------------------------------------------
__global__ __launch_bounds__(256) void row_fused(float* __restrict__ Wout) {
    __shared__ float sh[256];
    const int i = blockIdx.x;
    const int t = threadIdx.x;
    const int j0 = t * 16;
    const float inv_norm = 0.04419417382415922f;  // 1/sqrt(512)

    const float* Sl = g_S4 + 0 * (size_t)S * S + (size_t)i * S;
    const float* Sr = g_S4 + 1 * (size_t)S * S + (size_t)i * S;
    const float* Sg = g_S4 + 2 * (size_t)S * S + (size_t)i * S;
    const float* Sp = g_S4 + 3 * (size_t)S * S + (size_t)i * S;

    float lcdf[16], rcdf[16];

    {  // left boundary
        float e[16];
        float m = -1e30f;
#pragma unroll
        for (int u4 = 0; u4 < 4; u4++) {
            float4 v = *reinterpret_cast<const float4*>(Sl + j0 + 4 * u4);
            e[4 * u4 + 0] = v.x; e[4 * u4 + 1] = v.y;
            e[4 * u4 + 2] = v.z; e[4 * u4 + 3] = v.w;
        }
#pragma unroll
        for (int u = 0; u < 16; u++) {
            int j = j0 + u;
            float s = (j <= i) ? e[u] * inv_norm : -1e30f;
            e[u] = s;
            m = fmaxf(m, s);
        }
        m = blockMax(m, sh);
        float lsum = 0.0f;
#pragma unroll
        for (int u = 0; u < 16; u++) {
            int j = j0 + u;
            float ev = (j <= i) ? __expf(e[u] - m) : 0.0f;
            e[u] = ev;
            lsum += ev;
        }
        float tot;
        float incl = blockScanIncl(lsum, sh, &tot);
        float off = incl - lsum;
        float inv = 1.0f / tot;
        float c = 0.0f;
#pragma unroll
        for (int u = 0; u < 16; u++) {
            c += e[u];
            lcdf[u] = (c + off) * inv;
        }
    }

    {  // right boundary
        float e[16];
        float m = -1e30f;
#pragma unroll
        for (int u4 = 0; u4 < 4; u4++) {
            float4 v = *reinterpret_cast<const float4*>(Sr + j0 + 4 * u4);
            e[4 * u4 + 0] = v.x; e[4 * u4 + 1] = v.y;
            e[4 * u4 + 2] = v.z; e[4 * u4 + 3] = v.w;
        }
#pragma unroll
        for (int u = 0; u < 16; u++) {
            int j = j0 + u;
            float s = (j >= i) ? e[u] * inv_norm : -1e30f;
            e[u] = s;
            m = fmaxf(m, s);
        }
        m = blockMax(m, sh);
        float rsum = 0.0f;
#pragma unroll
        for (int u = 0; u < 16; u++) {
            int j = j0 + u;
            float ev = (j >= i) ? __expf(e[u] - m) : 0.0f;
            e[u] = ev;
            rsum += ev;
        }
        float tot;
        float incl = blockScanIncl(rsum, sh, &tot);
        float suff = tot - incl;
        float inv = 1.0f / tot;
        float c = 0.0f;
#pragma unroll
        for (int u = 15; u >= 0; u--) {
            c += e[u];
            rcdf[u] = (c + suff) * inv;
        }
    }

    {  // combine + final softmax
        float w[16], p[16];
#pragma unroll
        for (int u4 = 0; u4 < 4; u4++) {
            float4 vg = *reinterpret_cast<const float4*>(Sg + j0 + 4 * u4);
            float4 vp = *reinterpret_cast<const float4*>(Sp + j0 + 4 * u4);
            w[4 * u4 + 0] = vg.x; w[4 * u4 + 1] = vg.y;
            w[4 * u4 + 2] = vg.z; w[4 * u4 + 3] = vg.w;
            p[4 * u4 + 0] = vp.x; p[4 * u4 + 1] = vp.y;
            p[4 * u4 + 2] = vp.z; p[4 * u4 + 3] = vp.w;
        }
        float m = -1e30f;
#pragma unroll
        for (int u = 0; u < 16; u++) {
            float sc = (w[u] + p[u] * lcdf[u] * rcdf[u]) * inv_norm;
            w[u] = sc;
            m = fmaxf(m, sc);
        }
        m = blockMax(m, sh);
        float lsum = 0.0f;
#pragma unroll
        for (int u = 0; u < 16; u++) {
            float ev = __expf(w[u] - m);
            w[u] = ev;
            lsum += ev;
        }
        float tot = blockSum(lsum, sh);
        float inv = 1.0f / tot;
        float* Wrow = Wout + (size_t)i * S + j0;
        __nv_bfloat16* Hrow = g_Wh + (size_t)i * S + j0;
        __nv_bfloat16* Lrow = g_Wl + (size_t)i * S + j0;
#pragma unroll
        for (int u4 = 0; u4 < 4; u4++) {
            float4 o;
            o.x = w[4 * u4 + 0] * inv;
            o.y = w[4 * u4 + 1] * inv;
            o.z = w[4 * u4 + 2] * inv;
            o.w = w[4 * u4 + 3] * inv;
            *reinterpret_cast<float4*>(Wrow + 4 * u4) = o;
            float vv[4] = {o.x, o.y, o.z, o.w};
#pragma unroll
            for (int u = 0; u < 4; u++) {
                __nv_bfloat16 h = __float2bfloat16(vv[u]);
                Hrow[4 * u4 + u] = h;
                Lrow[4 * u4 + u] = __float2bfloat16(vv[u] - __bfloat162float(h));
            }
        }
    }
}

// ---------------------------------------------------------------------------
// Launch. inputs: x, w_ql, w_kl, w_qr, w_kr, w_qg, w_kg, w_qloc, w_kloc, w_v
// Output layout: [att_output (S*D) | att_weight (S*S)]
// ---------------------------------------------------------------------------
extern "C" void kernel_launch(void* const* d_in, const int* in_sizes, int n_in,
                              void* d_out, int out_size) {
    const float* x = (const float*)d_in[0];
    const float* w[9];
    for (int i = 0; i < 9; i++) w[i] = (const float*)d_in[1 + i];

    float* out = (float*)d_out;
    float* Wout = out + SD;

    __nv_bfloat16 *Xh, *Xl, *WTh, *WTl, *Ph, *Pl, *VTh, *VTl, *Wh, *Wl;
    float* S4;
    cudaGetSymbolAddress((void**)&Xh, g_Xh);
    cudaGetSymbolAddress((void**)&Xl, g_Xl);
    cudaGetSymbolAddress((void**)&WTh, g_WTh);
    cudaGetSymbolAddress((void**)&WTl, g_WTl);
    cudaGetSymbolAddress((void**)&Ph, g_Ph);
    cudaGetSymbolAddress((void**)&Pl, g_Pl);
    cudaGetSymbolAddress((void**)&VTh, g_VTh);
    cudaGetSymbolAddress((void**)&VTl, g_VTl);
    cudaGetSymbolAddress((void**)&S4, g_S4);
    cudaGetSymbolAddress((void**)&Wh, g_Wh);
    cudaGetSymbolAddress((void**)&Wl, g_Wl);

    cudaFuncSetAttribute(gemm_hmma<MODE_F32>,
                         cudaFuncAttributeMaxDynamicSharedMemorySize, SMEM_SZ);
    cudaFuncSetAttribute(gemm_hmma<MODE_SPLIT>,
                         cudaFuncAttributeMaxDynamicSharedMemorySize, SMEM_SZ);
    cudaFuncSetAttribute(gemm_hmma<MODE_SPLIT_T>,
                         cudaFuncAttributeMaxDynamicSharedMemorySize, SMEM_SZ);

    // 1) fp32 -> bf16 hi/lo splits of x and transposed weights
    split_x<<<SD / 256, 256>>>(x, Xh, Xl);
    for (int i = 0; i < 9; i++)
        splitT_w<<<DD / 256, 256>>>(w[i], WTh + i * DD, WTl + i * DD);

    // 2) projections on HMMA (bf16x3); v written transposed
    dim3 gp(D / 128, S / 128);
    for (int i = 0; i < 8; i++)
        gemm_hmma<MODE_SPLIT><<<gp, 256, SMEM_SZ>>>(
            Xh, Xl, WTh + i * DD, WTl + i * DD,
            nullptr, Ph + (size_t)i * SD, Pl + (size_t)i * SD, S, D, D);
    gemm_hmma<MODE_SPLIT_T><<<gp, 256, SMEM_SZ>>>(
        Xh, Xl, WTh + 8 * DD, WTl + 8 * DD, nullptr, VTh, VTl, S, D, D);

    // 3) four S x S score matrices: Q @ K^T
    dim3 gs(S / 128, S / 128);
    for (int q = 0; q < 4; q++)
        gemm_hmma<MODE_F32><<<gs, 256, SMEM_SZ>>>(
            Ph + (size_t)(2 * q) * SD, Pl + (size_t)(2 * q) * SD,
            Ph + (size_t)(2 * q + 1) * SD, Pl + (size_t)(2 * q + 1) * SD,
            S4 + (size_t)q * S * S, nullptr, nullptr, S, S, D);

    // 4) fused boundary softmaxes + cumsums + combine + final softmax
    row_fused<<<S, 256>>>(Wout);

    // 5) att_output = att_weight @ v   (W bf16x3  x  V^T bf16x3)
    dim3 gf(D / 128, S / 128);
    gemm_hmma<MODE_F32><<<gf, 256, SMEM_SZ>>>(
        Wh, Wl, VTh, VTl, out, nullptr, nullptr, S, D, S);
}

// round 4
// speedup vs baseline: 2.7697x; 1.0364x over previous
#include <cuda_runtime.h>
#include <cuda_bf16.h>
#include <cstdint>

#define S 4096
#define D 512
#define SD (S * D)
#define DD (D * D)
#define PCN 4096  // concatenated projection width (8 * 512)

// ---------------------------------------------------------------------------
// Scratch (__device__ globals; no allocations allowed)
// ---------------------------------------------------------------------------
__device__ __nv_bfloat16 g_Xh[SD], g_Xl[SD];
__device__ __nv_bfloat16 g_WTc_h[8 * DD], g_WTc_l[8 * DD];  // [4096 n][512 k]
__device__ __nv_bfloat16 g_WTv_h[DD], g_WTv_l[DD];          // [512 n][512 k]
__device__ __nv_bfloat16 g_Pc_h[(size_t)S * PCN], g_Pc_l[(size_t)S * PCN];
__device__ __nv_bfloat16 g_VTh[SD], g_VTl[SD];              // [512 n][4096 k]
__device__ float g_S4[4 * (size_t)S * S];
__device__ __nv_bfloat16 g_Wh[(size_t)S * S], g_Wl[(size_t)S * S];

// ---------------------------------------------------------------------------
// PTX helpers (baseline PTX only; legal on compute_103)
// ---------------------------------------------------------------------------
__device__ __forceinline__ uint32_t smem_u32(const void* p) {
    uint32_t a;
    asm("{ .reg .u64 t; cvta.to.shared.u64 t, %1; cvt.u32.u64 %0, t; }"
        : "=r"(a) : "l"(p));
    return a;
}

#define CP_ASYNC16(dst, src) \
    asm volatile("cp.async.cg.shared.global [%0], [%1], 16;" :: "r"(dst), "l"(src))
#define CP_COMMIT() asm volatile("cp.async.commit_group;" ::: "memory")
#define CP_WAIT1()  asm volatile("cp.async.wait_group 1;" ::: "memory")

__device__ __forceinline__ void ldsm4(uint32_t* r, uint32_t addr) {
    asm volatile("ldmatrix.sync.aligned.m8n8.x4.shared.b16 {%0,%1,%2,%3}, [%4];"
                 : "=r"(r[0]), "=r"(r[1]), "=r"(r[2]), "=r"(r[3]) : "r"(addr));
}

__device__ __forceinline__ void mma16816(float* c, const uint32_t* a,
                                         const uint32_t* b) {
    asm volatile(
        "mma.sync.aligned.m16n8k16.row.col.f32.bf16.bf16.f32 "
        "{%0,%1,%2,%3}, {%4,%5,%6,%7}, {%8,%9}, {%0,%1,%2,%3};"
        : "+f"(c[0]), "+f"(c[1]), "+f"(c[2]), "+f"(c[3])
        : "r"(a[0]), "r"(a[1]), "r"(a[2]), "r"(a[3]), "r"(b[0]), "r"(b[1]));
}

// swizzled offset within an 8KB tile: 128 rows x 64B (4 x 16B slots)
__device__ __forceinline__ uint32_t swz(int r, int c16) {
    return (uint32_t)(r * 64 + ((c16 ^ ((r >> 1) & 3)) << 4));
}

// ---------------------------------------------------------------------------
// HMMA bf16x3 GEMM:  C[M,N] = Ah@Bh^T + Ah@Bl^T + Al@Bh^T   (A,B K-major)
// CTA 128x128, 8 warps (warp tile 64x32), K-chunk 32, 3-stage cp.async.
// grid.z batching via azoff/bzoff (element offsets) and czoff.
// MODE 0: fp32 C row-major.  MODE 1: bf16 hi/lo row-major.
// MODE 2: bf16 hi/lo transposed (CT[n*Mtot+m]).
// ---------------------------------------------------------------------------
enum { MODE_F32 = 0, MODE_SPLIT = 1, MODE_SPLIT_T = 2 };

constexpr int SMEM_SZ = 3 * 4 * 8192;  // 3 stages x 4 tiles x 8KB = 96KB

__device__ __forceinline__ void cp_chunk(
    uint32_t sbase, int st, const __nv_bfloat16* A0, const __nv_bfloat16* A1,
    const __nv_bfloat16* B0, const __nv_bfloat16* B1, int lda, int ldb,
    int kk, int t) {
    const int lr = t >> 1;
    const int lc0 = (t & 1) * 2;
    const __nv_bfloat16* G[4] = {A0, A1, B0, B1};
#pragma unroll
    for (int tile = 0; tile < 4; tile++) {
        const int ld = (tile < 2) ? lda : ldb;
        const char* gs = (const char*)(G[tile] + (size_t)lr * ld + kk);
#pragma unroll
        for (int i = 0; i < 2; i++) {
            int c16 = lc0 + i;
            uint32_t d = sbase + st * 32768 + tile * 8192 + swz(lr, c16);
            CP_ASYNC16(d, gs + c16 * 16);
        }
    }
    CP_COMMIT();
}

template <int MODE>
__global__ void __launch_bounds__(256, 1)
gemm_hmma(const __nv_bfloat16* __restrict__ Ah, const __nv_bfloat16* __restrict__ Al,
          const __nv_bfloat16* __restrict__ Bh, const __nv_bfloat16* __restrict__ Bl,
          float* __restrict__ C, __nv_bfloat16* __restrict__ Ch,
          __nv_bfloat16* __restrict__ Cl, int Mtot, int Ntot, int K,
          int lda, int ldb, int azoff, int bzoff, long long czoff) {
    extern __shared__ char sm[];
    const uint32_t sbase = smem_u32(sm);
    const int t = threadIdx.x, lid = t & 31, wid = t >> 5;
    const int wm = wid & 1, wn = wid >> 1;
    const int m0 = blockIdx.y * 128, n0 = blockIdx.x * 128;
    const size_t z = blockIdx.z;

    const __nv_bfloat16* A0 = Ah + (size_t)m0 * lda + z * azoff;
    const __nv_bfloat16* A1 = Al + (size_t)m0 * lda + z * azoff;
    const __nv_bfloat16* B0 = Bh + (size_t)n0 * ldb + z * bzoff;
    const __nv_bfloat16* B1 = Bl + (size_t)n0 * ldb + z * bzoff;
    C += z * czoff;

    float acc[4][4][4];
#pragma unroll
    for (int i = 0; i < 4; i++)
#pragma unroll
        for (int j = 0; j < 4; j++)
#pragma unroll
            for (int k = 0; k < 4; k++) acc[i][j][k] = 0.0f;

    const int NCH = K >> 5;

    // ldmatrix lane coords
    const int a_row = lid & 15;
    const int a_chi = lid >> 4;
    const int b_row = (lid & 7) + ((lid >> 4) << 3);
    const int b_chi = (lid >> 3) & 1;

    cp_chunk(sbase, 0, A0, A1, B0, B1, lda, ldb, 0, t);
    cp_chunk(sbase, 1, A0, A1, B0, B1, lda, ldb, 32, t);

    for (int c = 0; c < NCH; c++) {
        CP_WAIT1();
        __syncthreads();
        if (c + 2 < NCH)
            cp_chunk(sbase, (c + 2) % 3, A0, A1, B0, B1, lda, ldb, (c + 2) * 32, t);
        else
            CP_COMMIT();  // keep group accounting so WAIT1 drains chunk c+1

        const uint32_t base = sbase + (c % 3) * 32768;
#pragma unroll
        for (int q = 0; q < 2; q++) {
            uint32_t ahf[4][4], alf[4][4], bhf[4][2], blf[4][2];
#pragma unroll
            for (int am = 0; am < 4; am++) {
                int r = wm * 64 + am * 16 + a_row;
                uint32_t off = swz(r, q * 2 + a_chi);
                ldsm4(ahf[am], base + 0 * 8192 + off);
                ldsm4(alf[am], base + 1 * 8192 + off);
            }
#pragma unroll
            for (int g2 = 0; g2 < 2; g2++) {
                int r = wn * 32 + g2 * 16 + b_row;
                uint32_t off = swz(r, q * 2 + b_chi);
                uint32_t rh[4], rl[4];
                ldsm4(rh, base + 2 * 8192 + off);
                ldsm4(rl, base + 3 * 8192 + off);
                bhf[2 * g2 + 0][0] = rh[0]; bhf[2 * g2 + 0][1] = rh[1];
                bhf[2 * g2 + 1][0] = rh[2]; bhf[2 * g2 + 1][1] = rh[3];
                blf[2 * g2 + 0][0] = rl[0]; blf[2 * g2 + 0][1] = rl[1];
                blf[2 * g2 + 1][0] = rl[2]; blf[2 * g2 + 1][1] = rl[3];
            }
#pragma unroll
            for (int am = 0; am < 4; am++)
#pragma unroll
                for (int an = 0; an < 4; an++) {
                    mma16816(acc[am][an], ahf[am], bhf[an]);
                    mma16816(acc[am][an], ahf[am], blf[an]);
                    mma16816(acc[am][an], alf[am], bhf[an]);
                }
        }
    }

    // epilogue
    const int t4 = lid >> 2;
    const int n2 = (lid & 3) * 2;
#pragma unroll
    for (int am = 0; am < 4; am++) {
#pragma unroll
        for (int an = 0; an < 4; an++) {
            int m_lo = m0 + wm * 64 + am * 16 + t4;
            int n = n0 + wn * 32 + an * 8 + n2;
            float* a4 = acc[am][an];
            if (MODE == MODE_F32) {
                *(float2*)(C + (size_t)m_lo * Ntot + n) = make_float2(a4[0], a4[1]);
                *(float2*)(C + (size_t)(m_lo + 8) * Ntot + n) = make_float2(a4[2], a4[3]);
            } else if (MODE == MODE_SPLIT) {
#pragma unroll
                for (int h2 = 0; h2 < 2; h2++) {
                    int m = m_lo + 8 * h2;
                    float v0 = a4[2 * h2], v1 = a4[2 * h2 + 1];
                    __nv_bfloat16 h0 = __float2bfloat16(v0);
                    __nv_bfloat16 h1 = __float2bfloat16(v1);
                    __nv_bfloat162 hh; hh.x = h0; hh.y = h1;
                    __nv_bfloat162 ll;
                    ll.x = __float2bfloat16(v0 - __bfloat162float(h0));
                    ll.y = __float2bfloat16(v1 - __bfloat162float(h1));
                    *(__nv_bfloat162*)(Ch + (size_t)m * Ntot + n) = hh;
                    *(__nv_bfloat162*)(Cl + (size_t)m * Ntot + n) = ll;
                }
            } else {  // MODE_SPLIT_T
#pragma unroll
                for (int h2 = 0; h2 < 2; h2++) {
                    int m = m_lo + 8 * h2;
#pragma unroll
                    for (int e = 0; e < 2; e++) {
                        float v = a4[2 * h2 + e];
                        __nv_bfloat16 h = __float2bfloat16(v);
                        Ch[(size_t)(n + e) * Mtot + m] = h;
                        Cl[(size_t)(n + e) * Mtot + m] =
                            __float2bfloat16(v - __bfloat162float(h));
                    }
                }
            }
        }
    }
}

// ---------------------------------------------------------------------------
// splits
// ---------------------------------------------------------------------------
__global__ void split_x(const float* __restrict__ x, __nv_bfloat16* __restrict__ xh,
                        __nv_bfloat16* __restrict__ xl) {
    int i = blockIdx.x * 256 + threadIdx.x;
    float v = x[i];
    __nv_bfloat16 h = __float2bfloat16(v);
    xh[i] = h;
    xl[i] = __float2bfloat16(v - __bfloat162float(h));
}

struct W9 { const float* p[9]; };

// transpose + split all 9 weights; one launch, coalesced via shared tile
__global__ void splitT_all(W9 w9, __nv_bfloat16* __restrict__ WTc_h,
                           __nv_bfloat16* __restrict__ WTc_l,
                           __nv_bfloat16* __restrict__ WTv_h,
                           __nv_bfloat16* __restrict__ WTv_l) {
    __shared__ float tile[32][33];
    const int tx = threadIdx.x, ty = threadIdx.y;
    const int kt = blockIdx.x * 32, nt = blockIdx.y * 32;
    const int wi = blockIdx.z;
    const float* w = w9.p[wi];
#pragma unroll
    for (int j = 0; j < 4; j++) {
        int r = ty + 8 * j;
        tile[r][tx] = w[(size_t)(kt + r) * D + nt + tx];
    }
    __syncthreads();
#pragma unroll
    for (int j = 0; j < 4; j++) {
        int n_loc = ty + 8 * j;
        float v = tile[tx][n_loc];
        __nv_bfloat16 h = __float2bfloat16(v);
        __nv_bfloat16 l = __float2bfloat16(v - __bfloat162float(h));
        if (wi < 8) {
            size_t o = (size_t)(wi * 512 + nt + n_loc) * D + kt + tx;
            WTc_h[o] = h;
            WTc_l[o] = l;
        } else {
            size_t o = (size_t)(nt + n_loc) * D + kt + tx;
            WTv_h[o] = h;
            WTv_l[o] = l;
        }
    }
}

// ---------------------------------------------------------------------------
// warp-shuffle block helpers (256 threads, 8 warps)
// ---------------------------------------------------------------------------
__device__ __forceinline__ float wmax(float v) {
#pragma unroll
    for (int o = 16; o; o >>= 1) v = fmaxf(v, __shfl_xor_sync(0xffffffffu, v, o));
    return v;
}
__device__ __forceinline__ float blockMax8(float v, float* sw, int w, int l) {
    v = wmax(v);
    if (l == 0) sw[w] = v;
    __syncthreads();
    float r = sw[0];
#pragma unroll
    for (int k = 1; k < 8; k++) r = fmaxf(r, sw[k]);
    __syncthreads();
    return r;
}
__device__ __forceinline__ float blockSum8(float v, float* sw, int w, int l) {
#pragma unroll
    for (int o = 16; o; o >>= 1) v += __shfl_xor_sync(0xffffffffu, v, o);
    if (l == 0) sw[w] = v;
    __syncthreads();
    float r = 0.0f;
#pragma unroll
    for (int k = 0; k < 8; k++) r += sw[k];
    __syncthreads();
    return r;
}
// returns EXCLUSIVE prefix of s across the block; *tot = block total
__device__ __forceinline__ float blockScanExcl(float s, float* sw, int w, int l,
                                               float* tot) {
    float incl = s;
#pragma unroll
    for (int o = 1; o < 32; o <<= 1) {
        float x = __shfl_up_sync(0xffffffffu, incl, o);
        if (l >= o) incl += x;
    }
    if (l == 31) sw[w] = incl;
    __syncthreads();
    float woff = 0.0f, tt = 0.0f;
#pragma unroll
    for (int k = 0; k < 8; k++) {
        float sv = sw[k];
        tt += sv;
        if (k < w) woff += sv;
    }
    __syncthreads();
    *tot = tt;
    return incl - s + woff;
}

// ---------------------------------------------------------------------------
// Fused per-row pipeline (also emits bf16 hi/lo of att_weight)
// ---------------------------------------------------------------------------
__global__ __launch_bounds__(256) void row_fused(float* __restrict__ Wout) {
    __shared__ float sw[8];
    const int i = blockIdx.x;
    const int t = threadIdx.x;
    const int w = t >> 5, l = t & 31;
    const int j0 = t * 16;
    const float inv_norm = 0.04419417382415922f;  // 1/sqrt(512)

    const float* Sl = g_S4 + 0 * (size_t)S * S + (size_t)i * S;
    const float* Sr = g_S4 + 1 * (size_t)S * S + (size_t)i * S;
    const float* Sg = g_S4 + 2 * (size_t)S * S + (size_t)i * S;
    const float* Sp = g_S4 + 3 * (size_t)S * S + (size_t)i * S;

    float lcdf[16], rcdf[16];

    {  // left boundary
        float e[16];
        float m = -1e30f;
#pragma unroll
        for (int u4 = 0; u4 < 4; u4++) {
            float4 v = *reinterpret_cast<const float4*>(Sl + j0 + 4 * u4);
            e[4 * u4 + 0] = v.x; e[4 * u4 + 1] = v.y;
            e[4 * u4 + 2] = v.z; e[4 * u4 + 3] = v.w;
        }
#pragma unroll
        for (int u = 0; u < 16; u++) {
            int j = j0 + u;
            float s = (j <= i) ? e[u] * inv_norm : -1e30f;
            e[u] = s;
            m = fmaxf(m, s);
        }
        m = blockMax8(m, sw, w, l);
        float lsum = 0.0f;
#pragma unroll
        for (int u = 0; u < 16; u++) {
            int j = j0 + u;
            float ev = (j <= i) ? __expf(e[u] - m) : 0.0f;
            e[u] = ev;
            lsum += ev;
        }
        float tot;
        float off = blockScanExcl(lsum, sw, w, l, &tot);
        float inv = 1.0f / tot;
        float c = 0.0f;
#pragma unroll
        for (int u = 0; u < 16; u++) {
            c += e[u];
            lcdf[u] = (c + off) * inv;
        }
    }

    {  // right boundary
        float e[16];
        float m = -1e30f;
#pragma unroll
        for (int u4 = 0; u4 < 4; u4++) {
            float4 v = *reinterpret_cast<const float4*>(Sr + j0 + 4 * u4);
            e[4 * u4 + 0] = v.x; e[4 * u4 + 1] = v.y;
            e[4 * u4 + 2] = v.z; e[4 * u4 + 3] = v.w;
        }
#pragma unroll
        for (int u = 0; u < 16; u++) {
            int j = j0 + u;
            float s = (j >= i) ? e[u] * inv_norm : -1e30f;
            e[u] = s;
            m = fmaxf(m, s);
        }
        m = blockMax8(m, sw, w, l);
        float rsum = 0.0f;
#pragma unroll
        for (int u = 0; u < 16; u++) {
            int j = j0 + u;
            float ev = (j >= i) ? __expf(e[u] - m) : 0.0f;
            e[u] = ev;
            rsum += ev;
        }
        float tot;
        float excl = blockScanExcl(rsum, sw, w, l, &tot);
        float suff = tot - excl - rsum;
        float inv = 1.0f / tot;
        float c = 0.0f;
#pragma unroll
        for (int u = 15; u >= 0; u--) {
            c += e[u];
            rcdf[u] = (c + suff) * inv;
        }
    }

    {  // combine + final softmax
        float wv[16], p[16];
#pragma unroll
        for (int u4 = 0; u4 < 4; u4++) {
            float4 vg = *reinterpret_cast<const float4*>(Sg + j0 + 4 * u4);
            float4 vp = *reinterpret_cast<const float4*>(Sp + j0 + 4 * u4);
            wv[4 * u4 + 0] = vg.x; wv[4 * u4 + 1] = vg.y;
            wv[4 * u4 + 2] = vg.z; wv[4 * u4 + 3] = vg.w;
            p[4 * u4 + 0] = vp.x; p[4 * u4 + 1] = vp.y;
            p[4 * u4 + 2] = vp.z; p[4 * u4 + 3] = vp.w;
        }
        float m = -1e30f;
#pragma unroll
        for (int u = 0; u < 16; u++) {
            float sc = (wv[u] + p[u] * lcdf[u] * rcdf[u]) * inv_norm;
            wv[u] = sc;
            m = fmaxf(m, sc);
        }
        m = blockMax8(m, sw, w, l);
        float lsum = 0.0f;
#pragma unroll
        for (int u = 0; u < 16; u++) {
            float ev = __expf(wv[u] - m);
            wv[u] = ev;
            lsum += ev;
        }
        float tot = blockSum8(lsum, sw, w, l);
        float inv = 1.0f / tot;
        float* Wrow = Wout + (size_t)i * S + j0;
        __nv_bfloat16* Hrow = g_Wh + (size_t)i * S + j0;
        __nv_bfloat16* Lrow = g_Wl + (size_t)i * S + j0;
#pragma unroll
        for (int u4 = 0; u4 < 4; u4++) {
            float4 o;
            o.x = wv[4 * u4 + 0] * inv;
            o.y = wv[4 * u4 + 1] * inv;
            o.z = wv[4 * u4 + 2] * inv;
            o.w = wv[4 * u4 + 3] * inv;
            *reinterpret_cast<float4*>(Wrow + 4 * u4) = o;
            float vv[4] = {o.x, o.y, o.z, o.w};
#pragma unroll
            for (int u = 0; u < 4; u++) {
                __nv_bfloat16 h = __float2bfloat16(vv[u]);
                Hrow[4 * u4 + u] = h;
                Lrow[4 * u4 + u] = __float2bfloat16(vv[u] - __bfloat162float(h));
            }
        }
    }
}

// ---------------------------------------------------------------------------
// Launch. inputs: x, w_ql, w_kl, w_qr, w_kr, w_qg, w_kg, w_qloc, w_kloc, w_v
// Output layout: [att_output (S*D) | att_weight (S*S)]
// ---------------------------------------------------------------------------
extern "C" void kernel_launch(void* const* d_in, const int* in_sizes, int n_in,
                              void* d_out, int out_size) {
    const float* x = (const float*)d_in[0];
    W9 w9;
    for (int i = 0; i < 9; i++) w9.p[i] = (const float*)d_in[1 + i];

    float* out = (float*)d_out;
    float* Wout = out + SD;

    __nv_bfloat16 *Xh, *Xl, *WTc_h, *WTc_l, *WTv_h, *WTv_l;
    __nv_bfloat16 *Pc_h, *Pc_l, *VTh, *VTl, *Wh, *Wl;
    float* S4;
    cudaGetSymbolAddress((void**)&Xh, g_Xh);
    cudaGetSymbolAddress((void**)&Xl, g_Xl);
    cudaGetSymbolAddress((void**)&WTc_h, g_WTc_h);
    cudaGetSymbolAddress((void**)&WTc_l, g_WTc_l);
    cudaGetSymbolAddress((void**)&WTv_h, g_WTv_h);
    cudaGetSymbolAddress((void**)&WTv_l, g_WTv_l);
    cudaGetSymbolAddress((void**)&Pc_h, g_Pc_h);
    cudaGetSymbolAddress((void**)&Pc_l, g_Pc_l);
    cudaGetSymbolAddress((void**)&VTh, g_VTh);
    cudaGetSymbolAddress((void**)&VTl, g_VTl);
    cudaGetSymbolAddress((void**)&S4, g_S4);
    cudaGetSymbolAddress((void**)&Wh, g_Wh);
    cudaGetSymbolAddress((void**)&Wl, g_Wl);

    cudaFuncSetAttribute(gemm_hmma<MODE_F32>,
                         cudaFuncAttributeMaxDynamicSharedMemorySize, SMEM_SZ);
    cudaFuncSetAttribute(gemm_hmma<MODE_SPLIT>,
                         cudaFuncAttributeMaxDynamicSharedMemorySize, SMEM_SZ);
    cudaFuncSetAttribute(gemm_hmma<MODE_SPLIT_T>,
                         cudaFuncAttributeMaxDynamicSharedMemorySize, SMEM_SZ);

    // 1) splits: x elementwise, weights transposed (one launch each)
    split_x<<<SD / 256, 256>>>(x, Xh, Xl);
    dim3 tb(32, 8);
    dim3 tg(D / 32, D / 32, 9);
    splitT_all<<<tg, tb>>>(w9, WTc_h, WTc_l, WTv_h, WTv_l);

    // 2) fused projections: Pcat[4096, 4096] = x @ [w_ql|w_kl|...|w_kloc]
    dim3 gp(PCN / 128, S / 128, 1);
    gemm_hmma<MODE_SPLIT><<<gp, 256, SMEM_SZ>>>(
        Xh, Xl, WTc_h, WTc_l, nullptr, Pc_h, Pc_l,
        S, PCN, D, D, D, 0, 0, 0);

    //    v projection, written transposed: VT[512, 4096]
    dim3 gv(D / 128, S / 128, 1);
    gemm_hmma<MODE_SPLIT_T><<<gv, 256, SMEM_SZ>>>(
        Xh, Xl, WTv_h, WTv_l, nullptr, VTh, VTl,
        S, D, D, D, D, 0, 0, 0);

    // 3) four S x S score matrices in ONE batched launch (z = 0..3)
    //    A = Pcat cols [2z*512, ...), B = Pcat cols [(2z+1)*512, ...)
    dim3 gs(S / 128, S / 128, 4);
    gemm_hmma<MODE_F32><<<gs, 256, SMEM_SZ>>>(
        Pc_h, Pc_l, Pc_h + 512, Pc_l + 512, S4, nullptr, nullptr,
        S, S, D, PCN, PCN, 1024, 1024, (long long)S * S);

    // 4) fused boundary softmaxes + cumsums + combine + final softmax
    row_fused<<<S, 256>>>(Wout);

    // 5) att_output = att_weight @ v   (W bf16x3  x  V^T bf16x3)
    dim3 gf(D / 128, S / 128, 1);
    gemm_hmma<MODE_F32><<<gf, 256, SMEM_SZ>>>(
        Wh, Wl, VTh, VTl, out, nullptr, nullptr,
        S, D, S, S, S, 0, 0, 0);
}

// round 5
// speedup vs baseline: 2.8256x; 1.0202x over previous
#include <cuda_runtime.h>
#include <cuda_bf16.h>
#include <cstdint>

#define S 4096
#define D 512
#define SD (S * D)
#define DD (D * D)
#define PCN 4096  // concatenated projection width (8 * 512)

// ---------------------------------------------------------------------------
// Scratch (__device__ globals; no allocations allowed)
// ---------------------------------------------------------------------------
__device__ __nv_bfloat16 g_Xh[SD], g_Xl[SD];
__device__ __nv_bfloat16 g_WTc_h[8 * DD], g_WTc_l[8 * DD];  // [4096 n][512 k]
__device__ __nv_bfloat16 g_WTv_h[DD], g_WTv_l[DD];          // [512 n][512 k]
__device__ __nv_bfloat16 g_Pc_h[(size_t)S * PCN], g_Pc_l[(size_t)S * PCN];
__device__ __nv_bfloat16 g_VTh[SD], g_VTl[SD];              // [512 n][4096 k]
__device__ float g_S4[4 * (size_t)S * S];
__device__ __nv_bfloat16 g_Wh[(size_t)S * S], g_Wl[(size_t)S * S];

// ---------------------------------------------------------------------------
// PTX helpers (baseline PTX only; legal on compute_103)
// ---------------------------------------------------------------------------
__device__ __forceinline__ uint32_t smem_u32(const void* p) {
    uint32_t a;
    asm("{ .reg .u64 t; cvta.to.shared.u64 t, %1; cvt.u32.u64 %0, t; }"
        : "=r"(a) : "l"(p));
    return a;
}

#define CP_ASYNC16(dst, src) \
    asm volatile("cp.async.cg.shared.global [%0], [%1], 16;" :: "r"(dst), "l"(src))
#define CP_COMMIT() asm volatile("cp.async.commit_group;" ::: "memory")
#define CP_WAIT1()  asm volatile("cp.async.wait_group 1;" ::: "memory")

__device__ __forceinline__ void ldsm4(uint32_t* r, uint32_t addr) {
    asm volatile("ldmatrix.sync.aligned.m8n8.x4.shared.b16 {%0,%1,%2,%3}, [%4];"
                 : "=r"(r[0]), "=r"(r[1]), "=r"(r[2]), "=r"(r[3]) : "r"(addr));
}

__device__ __forceinline__ void mma16816(float* c, const uint32_t* a,
                                         const uint32_t* b) {
    asm volatile(
        "mma.sync.aligned.m16n8k16.row.col.f32.bf16.bf16.f32 "
        "{%0,%1,%2,%3}, {%4,%5,%6,%7}, {%8,%9}, {%0,%1,%2,%3};"
        : "+f"(c[0]), "+f"(c[1]), "+f"(c[2]), "+f"(c[3])
        : "r"(a[0]), "r"(a[1]), "r"(a[2]), "r"(a[3]), "r"(b[0]), "r"(b[1]));
}

// swizzled offset within a 16KB tile: 128 rows x 128B (8 x 16B slots)
__device__ __forceinline__ uint32_t swz(int r, int c16) {
    return (uint32_t)(r * 128 + ((c16 ^ (r & 7)) << 4));
}

// ---------------------------------------------------------------------------
// HMMA bf16x3 GEMM:  C[M,N] = Ah@Bh^T + Ah@Bl^T + Al@Bh^T   (A,B K-major)
// CTA 128x128, 8 warps (warp tile 64x32), K-chunk 64, 3-stage cp.async,
// register double-buffered ldmatrix fragments.
// ---------------------------------------------------------------------------
enum { MODE_F32 = 0, MODE_SPLIT = 1, MODE_SPLIT_T = 2 };

constexpr int TILE_B = 16384;               // 128 rows x 128B
constexpr int STAGE_B = 4 * TILE_B;         // Ah, Al, Bh, Bl
constexpr int SMEM_SZ = 3 * STAGE_B;        // 192 KB

__device__ __forceinline__ void cp_chunk(
    uint32_t sbase, int st, const __nv_bfloat16* A0, const __nv_bfloat16* A1,
    const __nv_bfloat16* B0, const __nv_bfloat16* B1, int lda, int ldb,
    int kk, int t) {
    const int lr = t >> 1;             // row 0..127
    const int lc0 = (t & 1) * 4;       // first 16B slot (4 per half-row)
    const __nv_bfloat16* G[4] = {A0, A1, B0, B1};
#pragma unroll
    for (int tile = 0; tile < 4; tile++) {
        const int ld = (tile < 2) ? lda : ldb;
        const char* gs = (const char*)(G[tile] + (size_t)lr * ld + kk);
#pragma unroll
        for (int i = 0; i < 4; i++) {
            int c16 = lc0 + i;
            uint32_t d = sbase + st * STAGE_B + tile * TILE_B + swz(lr, c16);
            CP_ASYNC16(d, gs + c16 * 16);
        }
    }
    CP_COMMIT();
}

template <int MODE>
__global__ void __launch_bounds__(256, 1)
gemm_hmma(const __nv_bfloat16* __restrict__ Ah, const __nv_bfloat16* __restrict__ Al,
          const __nv_bfloat16* __restrict__ Bh, const __nv_bfloat16* __restrict__ Bl,
          float* __restrict__ C, __nv_bfloat16* __restrict__ Ch,
          __nv_bfloat16* __restrict__ Cl, int Mtot, int Ntot, int K,
          int lda, int ldb, int azoff, int bzoff, long long czoff) {
    extern __shared__ char sm[];
    const uint32_t sbase = smem_u32(sm);
    const int t = threadIdx.x, lid = t & 31, wid = t >> 5;
    const int wm = wid & 1, wn = wid >> 1;
    const int m0 = blockIdx.y * 128, n0 = blockIdx.x * 128;
    const size_t z = blockIdx.z;

    const __nv_bfloat16* A0 = Ah + (size_t)m0 * lda + z * azoff;
    const __nv_bfloat16* A1 = Al + (size_t)m0 * lda + z * azoff;
    const __nv_bfloat16* B0 = Bh + (size_t)n0 * ldb + z * bzoff;
    const __nv_bfloat16* B1 = Bl + (size_t)n0 * ldb + z * bzoff;
    C += z * czoff;

    float acc[4][4][4];
#pragma unroll
    for (int i = 0; i < 4; i++)
#pragma unroll
        for (int j = 0; j < 4; j++)
#pragma unroll
            for (int k = 0; k < 4; k++) acc[i][j][k] = 0.0f;

    const int NCH = K >> 6;  // 64-wide chunks

    // ldmatrix lane coords
    const int a_row = lid & 15;
    const int a_chi = lid >> 4;
    const int b_row = (lid & 7) + ((lid >> 4) << 3);
    const int b_chi = (lid >> 3) & 1;

    // double-buffered fragments
    uint32_t ahf[2][4][4], alf[2][4][4], bhf[2][4][2], blf[2][4][2];

#define LOAD_FRAGS(q, buf, base)                                               \
    do {                                                                       \
        _Pragma("unroll")                                                      \
        for (int am = 0; am < 4; am++) {                                       \
            int r_ = wm * 64 + am * 16 + a_row;                                \
            uint32_t off_ = swz(r_, (q) * 2 + a_chi);                          \
            ldsm4(ahf[buf][am], (base) + 0 * TILE_B + off_);                   \
            ldsm4(alf[buf][am], (base) + 1 * TILE_B + off_);                   \
        }                                                                      \
        _Pragma("unroll")                                                      \
        for (int g2 = 0; g2 < 2; g2++) {                                       \
            int r_ = wn * 32 + g2 * 16 + b_row;                                \
            uint32_t off_ = swz(r_, (q) * 2 + b_chi);                          \
            uint32_t rh_[4], rl_[4];                                           \
            ldsm4(rh_, (base) + 2 * TILE_B + off_);                            \
            ldsm4(rl_, (base) + 3 * TILE_B + off_);                            \
            bhf[buf][2 * g2 + 0][0] = rh_[0]; bhf[buf][2 * g2 + 0][1] = rh_[1];\
            bhf[buf][2 * g2 + 1][0] = rh_[2]; bhf[buf][2 * g2 + 1][1] = rh_[3];\
            blf[buf][2 * g2 + 0][0] = rl_[0]; blf[buf][2 * g2 + 0][1] = rl_[1];\
            blf[buf][2 * g2 + 1][0] = rl_[2]; blf[buf][2 * g2 + 1][1] = rl_[3];\
        }                                                                      \
    } while (0)

    cp_chunk(sbase, 0, A0, A1, B0, B1, lda, ldb, 0, t);
    cp_chunk(sbase, 1, A0, A1, B0, B1, lda, ldb, 64, t);

    for (int c = 0; c < NCH; c++) {
        CP_WAIT1();
        __syncthreads();
        if (c + 2 < NCH)
            cp_chunk(sbase, (c + 2) % 3, A0, A1, B0, B1, lda, ldb, (c + 2) * 64, t);
        else
            CP_COMMIT();  // keep group count so WAIT1 drains chunk c+1

        const uint32_t base = sbase + (c % 3) * STAGE_B;
        LOAD_FRAGS(0, 0, base);
#pragma unroll
        for (int q = 0; q < 4; q++) {
            if (q < 3) LOAD_FRAGS(q + 1, (q + 1) & 1, base);
            const int bf = q & 1;
#pragma unroll
            for (int am = 0; am < 4; am++)
#pragma unroll
                for (int an = 0; an < 4; an++) {
                    mma16816(acc[am][an], ahf[bf][am], bhf[bf][an]);
                    mma16816(acc[am][an], ahf[bf][am], blf[bf][an]);
                    mma16816(acc[am][an], alf[bf][am], bhf[bf][an]);
                }
        }
        __syncthreads();
    }
#undef LOAD_FRAGS

    // epilogue
    const int t4 = lid >> 2;
    const int n2 = (lid & 3) * 2;
#pragma unroll
    for (int am = 0; am < 4; am++) {
#pragma unroll
        for (int an = 0; an < 4; an++) {
            int m_lo = m0 + wm * 64 + am * 16 + t4;
            int n = n0 + wn * 32 + an * 8 + n2;
            float* a4 = acc[am][an];
            if (MODE == MODE_F32) {
                __stcs((float2*)(C + (size_t)m_lo * Ntot + n),
                       make_float2(a4[0], a4[1]));
                __stcs((float2*)(C + (size_t)(m_lo + 8) * Ntot + n),
                       make_float2(a4[2], a4[3]));
            } else if (MODE == MODE_SPLIT) {
#pragma unroll
                for (int h2 = 0; h2 < 2; h2++) {
                    int m = m_lo + 8 * h2;
                    float v0 = a4[2 * h2], v1 = a4[2 * h2 + 1];
                    __nv_bfloat16 h0 = __float2bfloat16(v0);
                    __nv_bfloat16 h1 = __float2bfloat16(v1);
                    __nv_bfloat162 hh; hh.x = h0; hh.y = h1;
                    __nv_bfloat162 ll;
                    ll.x = __float2bfloat16(v0 - __bfloat162float(h0));
                    ll.y = __float2bfloat16(v1 - __bfloat162float(h1));
                    *(__nv_bfloat162*)(Ch + (size_t)m * Ntot + n) = hh;
                    *(__nv_bfloat162*)(Cl + (size_t)m * Ntot + n) = ll;
                }
            } else {  // MODE_SPLIT_T
#pragma unroll
                for (int h2 = 0; h2 < 2; h2++) {
                    int m = m_lo + 8 * h2;
#pragma unroll
                    for (int e = 0; e < 2; e++) {
                        float v = a4[2 * h2 + e];
                        __nv_bfloat16 h = __float2bfloat16(v);
                        Ch[(size_t)(n + e) * Mtot + m] = h;
                        Cl[(size_t)(n + e) * Mtot + m] =
                            __float2bfloat16(v - __bfloat162float(h));
                    }
                }
            }
        }
    }
}

// ---------------------------------------------------------------------------
// splits
// ---------------------------------------------------------------------------
__global__ void split_x(const float* __restrict__ x, __nv_bfloat16* __restrict__ xh,
                        __nv_bfloat16* __restrict__ xl) {
    int i = blockIdx.x * 256 + threadIdx.x;
    float v = x[i];
    __nv_bfloat16 h = __float2bfloat16(v);
    xh[i] = h;
    xl[i] = __float2bfloat16(v - __bfloat162float(h));
}

struct W9 { const float* p[9]; };

// transpose + split all 9 weights; one launch, coalesced via shared tile
__global__ void splitT_all(W9 w9, __nv_bfloat16* __restrict__ WTc_h,
                           __nv_bfloat16* __restrict__ WTc_l,
                           __nv_bfloat16* __restrict__ WTv_h,
                           __nv_bfloat16* __restrict__ WTv_l) {
    __shared__ float tile[32][33];
    const int tx = threadIdx.x, ty = threadIdx.y;
    const int kt = blockIdx.x * 32, nt = blockIdx.y * 32;
    const int wi = blockIdx.z;
    const float* w = w9.p[wi];
#pragma unroll
    for (int j = 0; j < 4; j++) {
        int r = ty + 8 * j;
        tile[r][tx] = w[(size_t)(kt + r) * D + nt + tx];
    }
    __syncthreads();
#pragma unroll
    for (int j = 0; j < 4; j++) {
        int n_loc = ty + 8 * j;
        float v = tile[tx][n_loc];
        __nv_bfloat16 h = __float2bfloat16(v);
        __nv_bfloat16 l = __float2bfloat16(v - __bfloat162float(h));
        if (wi < 8) {
            size_t o = (size_t)(wi * 512 + nt + n_loc) * D + kt + tx;
            WTc_h[o] = h;
            WTc_l[o] = l;
        } else {
            size_t o = (size_t)(nt + n_loc) * D + kt + tx;
            WTv_h[o] = h;
            WTv_l[o] = l;
        }
    }
}

// ---------------------------------------------------------------------------
// warp-shuffle block helpers (256 threads, 8 warps)
// ---------------------------------------------------------------------------
__device__ __forceinline__ float wmax(float v) {
#pragma unroll
    for (int o = 16; o; o >>= 1) v = fmaxf(v, __shfl_xor_sync(0xffffffffu, v, o));
    return v;
}
__device__ __forceinline__ float blockMax8(float v, float* sw, int w, int l) {
    v = wmax(v);
    if (l == 0) sw[w] = v;
    __syncthreads();
    float r = sw[0];
#pragma unroll
    for (int k = 1; k < 8; k++) r = fmaxf(r, sw[k]);
    __syncthreads();
    return r;
}
__device__ __forceinline__ float blockSum8(float v, float* sw, int w, int l) {
#pragma unroll
    for (int o = 16; o; o >>= 1) v += __shfl_xor_sync(0xffffffffu, v, o);
    if (l == 0) sw[w] = v;
    __syncthreads();
    float r = 0.0f;
#pragma unroll
    for (int k = 0; k < 8; k++) r += sw[k];
    __syncthreads();
    return r;
}
// returns EXCLUSIVE prefix of s across the block; *tot = block total
__device__ __forceinline__ float blockScanExcl(float s, float* sw, int w, int l,
                                               float* tot) {
    float incl = s;
#pragma unroll
    for (int o = 1; o < 32; o <<= 1) {
        float x = __shfl_up_sync(0xffffffffu, incl, o);
        if (l >= o) incl += x;
    }
    if (l == 31) sw[w] = incl;
    __syncthreads();
    float woff = 0.0f, tt = 0.0f;
#pragma unroll
    for (int k = 0; k < 8; k++) {
        float sv = sw[k];
        tt += sv;
        if (k < w) woff += sv;
    }
    __syncthreads();
    *tot = tt;
    return incl - s + woff;
}

// ---------------------------------------------------------------------------
// Fused per-row pipeline (also emits bf16 hi/lo of att_weight)
// ---------------------------------------------------------------------------
__global__ __launch_bounds__(256) void row_fused(float* __restrict__ Wout) {
    __shared__ float sw[8];
    const int i = blockIdx.x;
    const int t = threadIdx.x;
    const int w = t >> 5, l = t & 31;
    const int j0 = t * 16;
    const float inv_norm = 0.04419417382415922f;  // 1/sqrt(512)

    const float* Sl = g_S4 + 0 * (size_t)S * S + (size_t)i * S;
    const float* Sr = g_S4 + 1 * (size_t)S * S + (size_t)i * S;
    const float* Sg = g_S4 + 2 * (size_t)S * S + (size_t)i * S;
    const float* Sp = g_S4 + 3 * (size_t)S * S + (size_t)i * S;

    float lcdf[16], rcdf[16];

    {  // left boundary
        float e[16];
        float m = -1e30f;
#pragma unroll
        for (int u4 = 0; u4 < 4; u4++) {
            float4 v = __ldcs(reinterpret_cast<const float4*>(Sl + j0 + 4 * u4));
            e[4 * u4 + 0] = v.x; e[4 * u4 + 1] = v.y;
            e[4 * u4 + 2] = v.z; e[4 * u4 + 3] = v.w;
        }
#pragma unroll
        for (int u = 0; u < 16; u++) {
            int j = j0 + u;
            float s = (j <= i) ? e[u] * inv_norm : -1e30f;
            e[u] = s;
            m = fmaxf(m, s);
        }
        m = blockMax8(m, sw, w, l);
        float lsum = 0.0f;
#pragma unroll
        for (int u = 0; u < 16; u++) {
            int j = j0 + u;
            float ev = (j <= i) ? __expf(e[u] - m) : 0.0f;
            e[u] = ev;
            lsum += ev;
        }
        float tot;
        float off = blockScanExcl(lsum, sw, w, l, &tot);
        float inv = 1.0f / tot;
        float c = 0.0f;
#pragma unroll
        for (int u = 0; u < 16; u++) {
            c += e[u];
            lcdf[u] = (c + off) * inv;
        }
    }

    {  // right boundary
        float e[16];
        float m = -1e30f;
#pragma unroll
        for (int u4 = 0; u4 < 4; u4++) {
            float4 v = __ldcs(reinterpret_cast<const float4*>(Sr + j0 + 4 * u4));
            e[4 * u4 + 0] = v.x; e[4 * u4 + 1] = v.y;
            e[4 * u4 + 2] = v.z; e[4 * u4 + 3] = v.w;
        }
#pragma unroll
        for (int u = 0; u < 16; u++) {
            int j = j0 + u;
            float s = (j >= i) ? e[u] * inv_norm : -1e30f;
            e[u] = s;
            m = fmaxf(m, s);
        }
        m = blockMax8(m, sw, w, l);
        float rsum = 0.0f;
#pragma unroll
        for (int u = 0; u < 16; u++) {
            int j = j0 + u;
            float ev = (j >= i) ? __expf(e[u] - m) : 0.0f;
            e[u] = ev;
            rsum += ev;
        }
        float tot;
        float excl = blockScanExcl(rsum, sw, w, l, &tot);
        float suff = tot - excl - rsum;
        float inv = 1.0f / tot;
        float c = 0.0f;
#pragma unroll
        for (int u = 15; u >= 0; u--) {
            c += e[u];
            rcdf[u] = (c + suff) * inv;
        }
    }

    {  // combine + final softmax
        float wv[16], p[16];
#pragma unroll
        for (int u4 = 0; u4 < 4; u4++) {
            float4 vg = __ldcs(reinterpret_cast<const float4*>(Sg + j0 + 4 * u4));
            float4 vp = __ldcs(reinterpret_cast<const float4*>(Sp + j0 + 4 * u4));
            wv[4 * u4 + 0] = vg.x; wv[4 * u4 + 1] = vg.y;
            wv[4 * u4 + 2] = vg.z; wv[4 * u4 + 3] = vg.w;
            p[4 * u4 + 0] = vp.x; p[4 * u4 + 1] = vp.y;
            p[4 * u4 + 2] = vp.z; p[4 * u4 + 3] = vp.w;
        }
        float m = -1e30f;
#pragma unroll
        for (int u = 0; u < 16; u++) {
            float sc = (wv[u] + p[u] * lcdf[u] * rcdf[u]) * inv_norm;
            wv[u] = sc;
            m = fmaxf(m, sc);
        }
        m = blockMax8(m, sw, w, l);
        float lsum = 0.0f;
#pragma unroll
        for (int u = 0; u < 16; u++) {
            float ev = __expf(wv[u] - m);
            wv[u] = ev;
            lsum += ev;
        }
        float tot = blockSum8(lsum, sw, w, l);
        float inv = 1.0f / tot;
        float* Wrow = Wout + (size_t)i * S + j0;
        __nv_bfloat16* Hrow = g_Wh + (size_t)i * S + j0;
        __nv_bfloat16* Lrow = g_Wl + (size_t)i * S + j0;
#pragma unroll
        for (int u4 = 0; u4 < 4; u4++) {
            float4 o;
            o.x = wv[4 * u4 + 0] * inv;
            o.y = wv[4 * u4 + 1] * inv;
            o.z = wv[4 * u4 + 2] * inv;
            o.w = wv[4 * u4 + 3] * inv;
            *reinterpret_cast<float4*>(Wrow + 4 * u4) = o;
            float vv[4] = {o.x, o.y, o.z, o.w};
#pragma unroll
            for (int u = 0; u < 4; u++) {
                __nv_bfloat16 h = __float2bfloat16(vv[u]);
                Hrow[4 * u4 + u] = h;
                Lrow[4 * u4 + u] = __float2bfloat16(vv[u] - __bfloat162float(h));
            }
        }
    }
}

// ---------------------------------------------------------------------------
// Launch. inputs: x, w_ql, w_kl, w_qr, w_kr, w_qg, w_kg, w_qloc, w_kloc, w_v
// Output layout: [att_output (S*D) | att_weight (S*S)]
// ---------------------------------------------------------------------------
extern "C" void kernel_launch(void* const* d_in, const int* in_sizes, int n_in,
                              void* d_out, int out_size) {
    const float* x = (const float*)d_in[0];
    W9 w9;
    for (int i = 0; i < 9; i++) w9.p[i] = (const float*)d_in[1 + i];

    float* out = (float*)d_out;
    float* Wout = out + SD;

    __nv_bfloat16 *Xh, *Xl, *WTc_h, *WTc_l, *WTv_h, *WTv_l;
    __nv_bfloat16 *Pc_h, *Pc_l, *VTh, *VTl, *Wh, *Wl;
    float* S4;
    cudaGetSymbolAddress((void**)&Xh, g_Xh);
    cudaGetSymbolAddress((void**)&Xl, g_Xl);
    cudaGetSymbolAddress((void**)&WTc_h, g_WTc_h);
    cudaGetSymbolAddress((void**)&WTc_l, g_WTc_l);
    cudaGetSymbolAddress((void**)&WTv_h, g_WTv_h);
    cudaGetSymbolAddress((void**)&WTv_l, g_WTv_l);
    cudaGetSymbolAddress((void**)&Pc_h, g_Pc_h);
    cudaGetSymbolAddress((void**)&Pc_l, g_Pc_l);
    cudaGetSymbolAddress((void**)&VTh, g_VTh);
    cudaGetSymbolAddress((void**)&VTl, g_VTl);
    cudaGetSymbolAddress((void**)&S4, g_S4);
    cudaGetSymbolAddress((void**)&Wh, g_Wh);
    cudaGetSymbolAddress((void**)&Wl, g_Wl);

    cudaFuncSetAttribute(gemm_hmma<MODE_F32>,
                         cudaFuncAttributeMaxDynamicSharedMemorySize, SMEM_SZ);
    cudaFuncSetAttribute(gemm_hmma<MODE_SPLIT>,
                         cudaFuncAttributeMaxDynamicSharedMemorySize, SMEM_SZ);
    cudaFuncSetAttribute(gemm_hmma<MODE_SPLIT_T>,
                         cudaFuncAttributeMaxDynamicSharedMemorySize, SMEM_SZ);

    // 1) splits: x elementwise, weights transposed (one launch each)
    split_x<<<SD / 256, 256>>>(x, Xh, Xl);
    dim3 tb(32, 8);
    dim3 tg(D / 32, D / 32, 9);
    splitT_all<<<tg, tb>>>(w9, WTc_h, WTc_l, WTv_h, WTv_l);

    // 2) fused projections: Pcat[4096, 4096] = x @ [w_ql|w_kl|...|w_kloc]
    dim3 gp(PCN / 128, S / 128, 1);
    gemm_hmma<MODE_SPLIT><<<gp, 256, SMEM_SZ>>>(
        Xh, Xl, WTc_h, WTc_l, nullptr, Pc_h, Pc_l,
        S, PCN, D, D, D, 0, 0, 0);

    //    v projection, written transposed: VT[512, 4096]
    dim3 gv(D / 128, S / 128, 1);
    gemm_hmma<MODE_SPLIT_T><<<gv, 256, SMEM_SZ>>>(
        Xh, Xl, WTv_h, WTv_l, nullptr, VTh, VTl,
        S, D, D, D, D, 0, 0, 0);

    // 3) four S x S score matrices in ONE batched launch (z = 0..3)
    dim3 gs(S / 128, S / 128, 4);
    gemm_hmma<MODE_F32><<<gs, 256, SMEM_SZ>>>(
        Pc_h, Pc_l, Pc_h + 512, Pc_l + 512, S4, nullptr, nullptr,
        S, S, D, PCN, PCN, 1024, 1024, (long long)S * S);

    // 4) fused boundary softmaxes + cumsums + combine + final softmax
    row_fused<<<S, 256>>>(Wout);

    // 5) att_output = att_weight @ v   (W bf16x3  x  V^T bf16x3)
    dim3 gf(D / 128, S / 128, 1);
    gemm_hmma<MODE_F32><<<gf, 256, SMEM_SZ>>>(
        Wh, Wl, VTh, VTl, out, nullptr, nullptr,
        S, D, S, S, S, 0, 0, 0);
}

// round 7
// speedup vs baseline: 2.8433x; 1.0063x over previous
#include <cuda_runtime.h>
#include <cuda_bf16.h>
#include <cstdint>

#define S 4096
#define D 512
#define SD (S * D)
#define DD (D * D)
#define PCN 4096  // concatenated projection width (8 * 512)

// ---------------------------------------------------------------------------
// Scratch (__device__ globals; no allocations allowed)
// ---------------------------------------------------------------------------
__device__ __nv_bfloat16 g_Xh[SD], g_Xl[SD];
__device__ __nv_bfloat16 g_WTc_h[8 * DD], g_WTc_l[8 * DD];  // [4096 n][512 k]
__device__ __nv_bfloat16 g_WTv_h[DD], g_WTv_l[DD];          // [512 n][512 k]
__device__ __nv_bfloat16 g_Pc_h[(size_t)S * PCN], g_Pc_l[(size_t)S * PCN];
__device__ __nv_bfloat16 g_VTh[SD], g_VTl[SD];              // [512 n][4096 k]
__device__ float g_S4[4 * (size_t)S * S];
__device__ __nv_bfloat16 g_Wh[(size_t)S * S], g_Wl[(size_t)S * S];

// ---------------------------------------------------------------------------
// PTX helpers (baseline PTX only; legal on compute_103)
// ---------------------------------------------------------------------------
__device__ __forceinline__ uint32_t smem_u32(const void* p) {
    uint32_t a;
    asm("{ .reg .u64 t; cvta.to.shared.u64 t, %1; cvt.u32.u64 %0, t; }"
        : "=r"(a) : "l"(p));
    return a;
}

#define CP_ASYNC16(dst, src) \
    asm volatile("cp.async.cg.shared.global [%0], [%1], 16;" :: "r"(dst), "l"(src))
#define CP_COMMIT() asm volatile("cp.async.commit_group;" ::: "memory")
#define CP_WAIT1()  asm volatile("cp.async.wait_group 1;" ::: "memory")

__device__ __forceinline__ void ldsm4(uint32_t* r, uint32_t addr) {
    asm volatile("ldmatrix.sync.aligned.m8n8.x4.shared.b16 {%0,%1,%2,%3}, [%4];"
                 : "=r"(r[0]), "=r"(r[1]), "=r"(r[2]), "=r"(r[3]) : "r"(addr));
}

__device__ __forceinline__ void mma16816(float* c, const uint32_t* a,
                                         const uint32_t* b) {
    asm volatile(
        "mma.sync.aligned.m16n8k16.row.col.f32.bf16.bf16.f32 "
        "{%0,%1,%2,%3}, {%4,%5,%6,%7}, {%8,%9}, {%0,%1,%2,%3};"
        : "+f"(c[0]), "+f"(c[1]), "+f"(c[2]), "+f"(c[3])
        : "r"(a[0]), "r"(a[1]), "r"(a[2]), "r"(a[3]), "r"(b[0]), "r"(b[1]));
}

// swizzled offset within a 16KB tile: 128 rows x 128B (8 x 16B slots)
__device__ __forceinline__ uint32_t swz(int r, int c16) {
    return (uint32_t)(r * 128 + ((c16 ^ (r & 7)) << 4));
}

// ---------------------------------------------------------------------------
// HMMA bf16x3 GEMM:  C[M,N] = Ah@Bh^T + Ah@Bl^T + Al@Bh^T   (A,B K-major)
// CTA 128x128, 8 warps (warp tile 64x32), K-chunk 64, 3-stage cp.async.
// MMA issue ordered BY PASS so same-accumulator HMMAs are 16 apart (no RAW
// chain on the tensor pipe).
// ---------------------------------------------------------------------------
enum { MODE_F32 = 0, MODE_SPLIT = 1, MODE_SPLIT_T = 2 };

constexpr int TILE_B = 16384;               // 128 rows x 128B
constexpr int STAGE_B = 4 * TILE_B;         // Ah, Al, Bh, Bl
constexpr int SMEM_SZ = 3 * STAGE_B;        // 192 KB

__device__ __forceinline__ void cp_chunk(
    uint32_t sbase, int st, const __nv_bfloat16* A0, const __nv_bfloat16* A1,
    const __nv_bfloat16* B0, const __nv_bfloat16* B1, int lda, int ldb,
    int kk, int t) {
    const int lr = t >> 1;             // row 0..127
    const int lc0 = (t & 1) * 4;       // first 16B slot (4 per half-row)
    const __nv_bfloat16* G[4] = {A0, A1, B0, B1};
#pragma unroll
    for (int tile = 0; tile < 4; tile++) {
        const int ld = (tile < 2) ? lda : ldb;
        const char* gs = (const char*)(G[tile] + (size_t)lr * ld + kk);
#pragma unroll
        for (int i = 0; i < 4; i++) {
            int c16 = lc0 + i;
            uint32_t d = sbase + st * STAGE_B + tile * TILE_B + swz(lr, c16);
            CP_ASYNC16(d, gs + c16 * 16);
        }
    }
    CP_COMMIT();
}

template <int MODE>
__global__ void __launch_bounds__(256, 1)
gemm_hmma(const __nv_bfloat16* __restrict__ Ah, const __nv_bfloat16* __restrict__ Al,
          const __nv_bfloat16* __restrict__ Bh, const __nv_bfloat16* __restrict__ Bl,
          float* __restrict__ C, __nv_bfloat16* __restrict__ Ch,
          __nv_bfloat16* __restrict__ Cl, int Mtot, int Ntot, int K,
          int lda, int ldb, int azoff, int bzoff, long long czoff) {
    extern __shared__ char sm[];
    const uint32_t sbase = smem_u32(sm);
    const int t = threadIdx.x, lid = t & 31, wid = t >> 5;
    const int wm = wid & 1, wn = wid >> 1;
    const int m0 = blockIdx.y * 128, n0 = blockIdx.x * 128;
    const size_t z = blockIdx.z;

    const __nv_bfloat16* A0 = Ah + (size_t)m0 * lda + z * azoff;
    const __nv_bfloat16* A1 = Al + (size_t)m0 * lda + z * azoff;
    const __nv_bfloat16* B0 = Bh + (size_t)n0 * ldb + z * bzoff;
    const __nv_bfloat16* B1 = Bl + (size_t)n0 * ldb + z * bzoff;
    C += z * czoff;

    float acc[4][4][4];
#pragma unroll
    for (int i = 0; i < 4; i++)
#pragma unroll
        for (int j = 0; j < 4; j++)
#pragma unroll
            for (int k = 0; k < 4; k++) acc[i][j][k] = 0.0f;

    const int NCH = K >> 6;  // 64-wide chunks

    // ldmatrix lane coords
    const int a_row = lid & 15;
    const int a_chi = lid >> 4;
    const int b_row = (lid & 7) + ((lid >> 4) << 3);
    const int b_chi = (lid >> 3) & 1;

    cp_chunk(sbase, 0, A0, A1, B0, B1, lda, ldb, 0, t);
    cp_chunk(sbase, 1, A0, A1, B0, B1, lda, ldb, 64, t);

    for (int c = 0; c < NCH; c++) {
        CP_WAIT1();
        __syncthreads();
        if (c + 2 < NCH)
            cp_chunk(sbase, (c + 2) % 3, A0, A1, B0, B1, lda, ldb, (c + 2) * 64, t);
        else
            CP_COMMIT();  // keep group count so WAIT1 drains chunk c+1

        const uint32_t base = sbase + (c % 3) * STAGE_B;
#pragma unroll
        for (int q = 0; q < 4; q++) {
            uint32_t ahf[4][4], alf[4][4], bhf[4][2], blf[4][2];
#pragma unroll
            for (int am = 0; am < 4; am++) {
                int r = wm * 64 + am * 16 + a_row;
                uint32_t off = swz(r, q * 2 + a_chi);
                ldsm4(ahf[am], base + 0 * TILE_B + off);
                ldsm4(alf[am], base + 1 * TILE_B + off);
            }
#pragma unroll
            for (int g2 = 0; g2 < 2; g2++) {
                int r = wn * 32 + g2 * 16 + b_row;
                uint32_t off = swz(r, q * 2 + b_chi);
                uint32_t rh[4], rl[4];
                ldsm4(rh, base + 2 * TILE_B + off);
                ldsm4(rl, base + 3 * TILE_B + off);
                bhf[2 * g2 + 0][0] = rh[0]; bhf[2 * g2 + 0][1] = rh[1];
                bhf[2 * g2 + 1][0] = rh[2]; bhf[2 * g2 + 1][1] = rh[3];
                blf[2 * g2 + 0][0] = rl[0]; blf[2 * g2 + 0][1] = rl[1];
                blf[2 * g2 + 1][0] = rl[2]; blf[2 * g2 + 1][1] = rl[3];
            }
            // pass-ordered: 16 independent MMAs between accumulator reuses
#pragma unroll
            for (int am = 0; am < 4; am++)
#pragma unroll
                for (int an = 0; an < 4; an++)
                    mma16816(acc[am][an], ahf[am], bhf[an]);
#pragma unroll
            for (int am = 0; am < 4; am++)
#pragma unroll
                for (int an = 0; an < 4; an++)
                    mma16816(acc[am][an], ahf[am], blf[an]);
#pragma unroll
            for (int am = 0; am < 4; am++)
#pragma unroll
                for (int an = 0; an < 4; an++)
                    mma16816(acc[am][an], alf[am], bhf[an]);
        }
        __syncthreads();
    }

    // epilogue
    const int t4 = lid >> 2;
    const int n2 = (lid & 3) * 2;
#pragma unroll
    for (int am = 0; am < 4; am++) {
#pragma unroll
        for (int an = 0; an < 4; an++) {
            int m_lo = m0 + wm * 64 + am * 16 + t4;
            int n = n0 + wn * 32 + an * 8 + n2;
            float* a4 = acc[am][an];
            if (MODE == MODE_F32) {
                __stcs((float2*)(C + (size_t)m_lo * Ntot + n),
                       make_float2(a4[0], a4[1]));
                __stcs((float2*)(C + (size_t)(m_lo + 8) * Ntot + n),
                       make_float2(a4[2], a4[3]));
            } else if (MODE == MODE_SPLIT) {
#pragma unroll
                for (int h2 = 0; h2 < 2; h2++) {
                    int m = m_lo + 8 * h2;
                    float v0 = a4[2 * h2], v1 = a4[2 * h2 + 1];
                    __nv_bfloat16 h0 = __float2bfloat16(v0);
                    __nv_bfloat16 h1 = __float2bfloat16(v1);
                    __nv_bfloat162 hh; hh.x = h0; hh.y = h1;
                    __nv_bfloat162 ll;
                    ll.x = __float2bfloat16(v0 - __bfloat162float(h0));
                    ll.y = __float2bfloat16(v1 - __bfloat162float(h1));
                    *(__nv_bfloat162*)(Ch + (size_t)m * Ntot + n) = hh;
                    *(__nv_bfloat162*)(Cl + (size_t)m * Ntot + n) = ll;
                }
            } else {  // MODE_SPLIT_T
#pragma unroll
                for (int h2 = 0; h2 < 2; h2++) {
                    int m = m_lo + 8 * h2;
#pragma unroll
                    for (int e = 0; e < 2; e++) {
                        float v = a4[2 * h2 + e];
                        __nv_bfloat16 h = __float2bfloat16(v);
                        Ch[(size_t)(n + e) * Mtot + m] = h;
                        Cl[(size_t)(n + e) * Mtot + m] =
                            __float2bfloat16(v - __bfloat162float(h));
                    }
                }
            }
        }
    }
}

// ---------------------------------------------------------------------------
// splits
// ---------------------------------------------------------------------------
__global__ void split_x(const float* __restrict__ x, __nv_bfloat16* __restrict__ xh,
                        __nv_bfloat16* __restrict__ xl) {
    int i = blockIdx.x * 256 + threadIdx.x;
    float v = x[i];
    __nv_bfloat16 h = __float2bfloat16(v);
    xh[i] = h;
    xl[i] = __float2bfloat16(v - __bfloat162float(h));
}

struct W9 { const float* p[9]; };

// transpose + split all 9 weights; one launch, coalesced via shared tile
__global__ void splitT_all(W9 w9, __nv_bfloat16* __restrict__ WTc_h,
                           __nv_bfloat16* __restrict__ WTc_l,
                           __nv_bfloat16* __restrict__ WTv_h,
                           __nv_bfloat16* __restrict__ WTv_l) {
    __shared__ float tile[32][33];
    const int tx = threadIdx.x, ty = threadIdx.y;
    const int kt = blockIdx.x * 32, nt = blockIdx.y * 32;
    const int wi = blockIdx.z;
    const float* w = w9.p[wi];
#pragma unroll
    for (int j = 0; j < 4; j++) {
        int r = ty + 8 * j;
        tile[r][tx] = w[(size_t)(kt + r) * D + nt + tx];
    }
    __syncthreads();
#pragma unroll
    for (int j = 0; j < 4; j++) {
        int n_loc = ty + 8 * j;
        float v = tile[tx][n_loc];
        __nv_bfloat16 h = __float2bfloat16(v);
        __nv_bfloat16 l = __float2bfloat16(v - __bfloat162float(h));
        if (wi < 8) {
            size_t o = (size_t)(wi * 512 + nt + n_loc) * D + kt + tx;
            WTc_h[o] = h;
            WTc_l[o] = l;
        } else {
            size_t o = (size_t)(nt + n_loc) * D + kt + tx;
            WTv_h[o] = h;
            WTv_l[o] = l;
        }
    }
}

// ---------------------------------------------------------------------------
// warp-shuffle block helpers (256 threads, 8 warps)
// ---------------------------------------------------------------------------
__device__ __forceinline__ float wmax(float v) {
#pragma unroll
    for (int o = 16; o; o >>= 1) v = fmaxf(v, __shfl_xor_sync(0xffffffffu, v, o));
    return v;
}
__device__ __forceinline__ float blockMax8(float v, float* sw, int w, int l) {
    v = wmax(v);
    if (l == 0) sw[w] = v;
    __syncthreads();
    float r = sw[0];
#pragma unroll
    for (int k = 1; k < 8; k++) r = fmaxf(r, sw[k]);
    __syncthreads();
    return r;
}
__device__ __forceinline__ float blockSum8(float v, float* sw, int w, int l) {
#pragma unroll
    for (int o = 16; o; o >>= 1) v += __shfl_xor_sync(0xffffffffu, v, o);
    if (l == 0) sw[w] = v;
    __syncthreads();
    float r = 0.0f;
#pragma unroll
    for (int k = 0; k < 8; k++) r += sw[k];
    __syncthreads();
    return r;
}
// returns EXCLUSIVE prefix of s across the block; *tot = block total
__device__ __forceinline__ float blockScanExcl(float s, float* sw, int w, int l,
                                               float* tot) {
    float incl = s;
#pragma unroll
    for (int o = 1; o < 32; o <<= 1) {
        float x = __shfl_up_sync(0xffffffffu, incl, o);
        if (l >= o) incl += x;
    }
    if (l == 31) sw[w] = incl;
    __syncthreads();
    float woff = 0.0f, tt = 0.0f;
#pragma unroll
    for (int k = 0; k < 8; k++) {
        float sv = sw[k];
        tt += sv;
        if (k < w) woff += sv;
    }
    __syncthreads();
    *tot = tt;
    return incl - s + woff;
}

// ---------------------------------------------------------------------------
// Fused per-row pipeline (also emits bf16 hi/lo of att_weight)
// ---------------------------------------------------------------------------
__global__ __launch_bounds__(256) void row_fused(float* __restrict__ Wout) {
    __shared__ float sw[8];
    const int i = blockIdx.x;
    const int t = threadIdx.x;
    const int w = t >> 5, l = t & 31;
    const int j0 = t * 16;
    const float inv_norm = 0.04419417382415922f;  // 1/sqrt(512)

    const float* Sl = g_S4 + 0 * (size_t)S * S + (size_t)i * S;
    const float* Sr = g_S4 + 1 * (size_t)S * S + (size_t)i * S;
    const float* Sg = g_S4 + 2 * (size_t)S * S + (size_t)i * S;
    const float* Sp = g_S4 + 3 * (size_t)S * S + (size_t)i * S;

    float lcdf[16], rcdf[16];

    {  // left boundary
        float e[16];
        float m = -1e30f;
#pragma unroll
        for (int u4 = 0; u4 < 4; u4++) {
            float4 v = __ldcs(reinterpret_cast<const float4*>(Sl + j0 + 4 * u4));
            e[4 * u4 + 0] = v.x; e[4 * u4 + 1] = v.y;
            e[4 * u4 + 2] = v.z; e[4 * u4 + 3] = v.w;
        }
#pragma unroll
        for (int u = 0; u < 16; u++) {
            int j = j0 + u;
            float s = (j <= i) ? e[u] * inv_norm : -1e30f;
            e[u] = s;
            m = fmaxf(m, s);
        }
        m = blockMax8(m, sw, w, l);
        float lsum = 0.0f;
#pragma unroll
        for (int u = 0; u < 16; u++) {
            int j = j0 + u;
            float ev = (j <= i) ? __expf(e[u] - m) : 0.0f;
            e[u] = ev;
            lsum += ev;
        }
        float tot;
        float off = blockScanExcl(lsum, sw, w, l, &tot);
        float inv = 1.0f / tot;
        float c = 0.0f;
#pragma unroll
        for (int u = 0; u < 16; u++) {
            c += e[u];
            lcdf[u] = (c + off) * inv;
        }
    }

    {  // right boundary
        float e[16];
        float m = -1e30f;
#pragma unroll
        for (int u4 = 0; u4 < 4; u4++) {
            float4 v = __ldcs(reinterpret_cast<const float4*>(Sr + j0 + 4 * u4));
            e[4 * u4 + 0] = v.x; e[4 * u4 + 1] = v.y;
            e[4 * u4 + 2] = v.z; e[4 * u4 + 3] = v.w;
        }
#pragma unroll
        for (int u = 0; u < 16; u++) {
            int j = j0 + u;
            float s = (j >= i) ? e[u] * inv_norm : -1e30f;
            e[u] = s;
            m = fmaxf(m, s);
        }
        m = blockMax8(m, sw, w, l);
        float rsum = 0.0f;
#pragma unroll
        for (int u = 0; u < 16; u++) {
            int j = j0 + u;
            float ev = (j >= i) ? __expf(e[u] - m) : 0.0f;
            e[u] = ev;
            rsum += ev;
        }
        float tot;
        float excl = blockScanExcl(rsum, sw, w, l, &tot);
        float suff = tot - excl - rsum;
        float inv = 1.0f / tot;
        float c = 0.0f;
#pragma unroll
        for (int u = 15; u >= 0; u--) {
            c += e[u];
            rcdf[u] = (c + suff) * inv;
        }
    }

    {  // combine + final softmax
        float wv[16], p[16];
#pragma unroll
        for (int u4 = 0; u4 < 4; u4++) {
            float4 vg = __ldcs(reinterpret_cast<const float4*>(Sg + j0 + 4 * u4));
            float4 vp = __ldcs(reinterpret_cast<const float4*>(Sp + j0 + 4 * u4));
            wv[4 * u4 + 0] = vg.x; wv[4 * u4 + 1] = vg.y;
            wv[4 * u4 + 2] = vg.z; wv[4 * u4 + 3] = vg.w;
            p[4 * u4 + 0] = vp.x; p[4 * u4 + 1] = vp.y;
            p[4 * u4 + 2] = vp.z; p[4 * u4 + 3] = vp.w;
        }
        float m = -1e30f;
#pragma unroll
        for (int u = 0; u < 16; u++) {
            float sc = (wv[u] + p[u] * lcdf[u] * rcdf[u]) * inv_norm;
            wv[u] = sc;
            m = fmaxf(m, sc);
        }
        m = blockMax8(m, sw, w, l);
        float lsum = 0.0f;
#pragma unroll
        for (int u = 0; u < 16; u++) {
            float ev = __expf(wv[u] - m);
            wv[u] = ev;
            lsum += ev;
        }
        float tot = blockSum8(lsum, sw, w, l);
        float inv = 1.0f / tot;
        float* Wrow = Wout + (size_t)i * S + j0;
        __nv_bfloat16* Hrow = g_Wh + (size_t)i * S + j0;
        __nv_bfloat16* Lrow = g_Wl + (size_t)i * S + j0;
#pragma unroll
        for (int u4 = 0; u4 < 4; u4++) {
            float4 o;
            o.x = wv[4 * u4 + 0] * inv;
            o.y = wv[4 * u4 + 1] * inv;
            o.z = wv[4 * u4 + 2] * inv;
            o.w = wv[4 * u4 + 3] * inv;
            *reinterpret_cast<float4*>(Wrow + 4 * u4) = o;
            float vv[4] = {o.x, o.y, o.z, o.w};
#pragma unroll
            for (int u = 0; u < 4; u++) {
                __nv_bfloat16 h = __float2bfloat16(vv[u]);
                Hrow[4 * u4 + u] = h;
                Lrow[4 * u4 + u] = __float2bfloat16(vv[u] - __bfloat162float(h));
            }
        }
    }
}

// ---------------------------------------------------------------------------
// Launch. inputs: x, w_ql, w_kl, w_qr, w_kr, w_qg, w_kg, w_qloc, w_kloc, w_v
// Output layout: [att_output (S*D) | att_weight (S*S)]
// ---------------------------------------------------------------------------
extern "C" void kernel_launch(void* const* d_in, const int* in_sizes, int n_in,
                              void* d_out, int out_size) {
    const float* x = (const float*)d_in[0];
    W9 w9;
    for (int i = 0; i < 9; i++) w9.p[i] = (const float*)d_in[1 + i];

    float* out = (float*)d_out;
    float* Wout = out + SD;

    __nv_bfloat16 *Xh, *Xl, *WTc_h, *WTc_l, *WTv_h, *WTv_l;
    __nv_bfloat16 *Pc_h, *Pc_l, *VTh, *VTl, *Wh, *Wl;
    float* S4;
    cudaGetSymbolAddress((void**)&Xh, g_Xh);
    cudaGetSymbolAddress((void**)&Xl, g_Xl);
    cudaGetSymbolAddress((void**)&WTc_h, g_WTc_h);
    cudaGetSymbolAddress((void**)&WTc_l, g_WTc_l);
    cudaGetSymbolAddress((void**)&WTv_h, g_WTv_h);
    cudaGetSymbolAddress((void**)&WTv_l, g_WTv_l);
    cudaGetSymbolAddress((void**)&Pc_h, g_Pc_h);
    cudaGetSymbolAddress((void**)&Pc_l, g_Pc_l);
    cudaGetSymbolAddress((void**)&VTh, g_VTh);
    cudaGetSymbolAddress((void**)&VTl, g_VTl);
    cudaGetSymbolAddress((void**)&S4, g_S4);
    cudaGetSymbolAddress((void**)&Wh, g_Wh);
    cudaGetSymbolAddress((void**)&Wl, g_Wl);

    cudaFuncSetAttribute(gemm_hmma<MODE_F32>,
                         cudaFuncAttributeMaxDynamicSharedMemorySize, SMEM_SZ);
    cudaFuncSetAttribute(gemm_hmma<MODE_SPLIT>,
                         cudaFuncAttributeMaxDynamicSharedMemorySize, SMEM_SZ);
    cudaFuncSetAttribute(gemm_hmma<MODE_SPLIT_T>,
                         cudaFuncAttributeMaxDynamicSharedMemorySize, SMEM_SZ);

    // 1) splits: x elementwise, weights transposed (one launch each)
    split_x<<<SD / 256, 256>>>(x, Xh, Xl);
    dim3 tb(32, 8);
    dim3 tg(D / 32, D / 32, 9);
    splitT_all<<<tg, tb>>>(w9, WTc_h, WTc_l, WTv_h, WTv_l);

    // 2) fused projections: Pcat[4096, 4096] = x @ [w_ql|w_kl|...|w_kloc]
    dim3 gp(PCN / 128, S / 128, 1);
    gemm_hmma<MODE_SPLIT><<<gp, 256, SMEM_SZ>>>(
        Xh, Xl, WTc_h, WTc_l, nullptr, Pc_h, Pc_l,
        S, PCN, D, D, D, 0, 0, 0);

    //    v projection, written transposed: VT[512, 4096]
    dim3 gv(D / 128, S / 128, 1);
    gemm_hmma<MODE_SPLIT_T><<<gv, 256, SMEM_SZ>>>(
        Xh, Xl, WTv_h, WTv_l, nullptr, VTh, VTl,
        S, D, D, D, D, 0, 0, 0);

    // 3) four S x S score matrices in ONE batched launch (z = 0..3)
    dim3 gs(S / 128, S / 128, 4);
    gemm_hmma<MODE_F32><<<gs, 256, SMEM_SZ>>>(
        Pc_h, Pc_l, Pc_h + 512, Pc_l + 512, S4, nullptr, nullptr,
        S, S, D, PCN, PCN, 1024, 1024, (long long)S * S);

    // 4) fused boundary softmaxes + cumsums + combine + final softmax
    row_fused<<<S, 256>>>(Wout);

    // 5) att_output = att_weight @ v   (W bf16x3  x  V^T bf16x3)
    dim3 gf(D / 128, S / 128, 1);
    gemm_hmma<MODE_F32><<<gf, 256, SMEM_SZ>>>(
        Wh, Wl, VTh, VTl, out, nullptr, nullptr,
        S, D, S, S, S, 0, 0, 0);
}

// round 8
// speedup vs baseline: 3.2595x; 1.1464x over previous
#include <cuda_runtime.h>
#include <cuda_bf16.h>
#include <cstdint>

#define S 4096
#define D 512
#define SD (S * D)
#define DD (D * D)
#define PCN 4096  // concatenated projection width (8 * 512)

// ---------------------------------------------------------------------------
// Scratch (__device__ globals; no allocations allowed)
// ---------------------------------------------------------------------------
__device__ __nv_bfloat16 g_Xh[SD], g_Xl[SD];
__device__ __nv_bfloat16 g_WTc_h[8 * DD], g_WTc_l[8 * DD];  // [4096 n][512 k]
__device__ __nv_bfloat16 g_WTv_h[DD], g_WTv_l[DD];          // [512 n][512 k]
__device__ __nv_bfloat16 g_Pc_h[(size_t)S * PCN], g_Pc_l[(size_t)S * PCN];
__device__ __nv_bfloat16 g_VTh[SD], g_VTl[SD];              // [512 n][4096 k]
__device__ float g_S4[4 * (size_t)S * S];
__device__ __nv_bfloat16 g_Wh[(size_t)S * S], g_Wl[(size_t)S * S];

// ---------------------------------------------------------------------------
// PTX helpers (baseline PTX only; legal on compute_103)
// ---------------------------------------------------------------------------
__device__ __forceinline__ uint32_t smem_u32(const void* p) {
    uint32_t a;
    asm("{ .reg .u64 t; cvta.to.shared.u64 t, %1; cvt.u32.u64 %0, t; }"
        : "=r"(a) : "l"(p));
    return a;
}

#define CP_ASYNC16(dst, src) \
    asm volatile("cp.async.cg.shared.global [%0], [%1], 16;" :: "r"(dst), "l"(src))
#define CP_COMMIT() asm volatile("cp.async.commit_group;" ::: "memory")
#define CP_WAIT1()  asm volatile("cp.async.wait_group 1;" ::: "memory")

__device__ __forceinline__ void ldsm4(uint32_t* r, uint32_t addr) {
    asm volatile("ldmatrix.sync.aligned.m8n8.x4.shared.b16 {%0,%1,%2,%3}, [%4];"
                 : "=r"(r[0]), "=r"(r[1]), "=r"(r[2]), "=r"(r[3]) : "r"(addr));
}

__device__ __forceinline__ void mma16816(float* c, const uint32_t* a,
                                         const uint32_t* b) {
    asm volatile(
        "mma.sync.aligned.m16n8k16.row.col.f32.bf16.bf16.f32 "
        "{%0,%1,%2,%3}, {%4,%5,%6,%7}, {%8,%9}, {%0,%1,%2,%3};"
        : "+f"(c[0]), "+f"(c[1]), "+f"(c[2]), "+f"(c[3])
        : "r"(a[0]), "r"(a[1]), "r"(a[2]), "r"(a[3]), "r"(b[0]), "r"(b[1]));
}

// swizzled offset within a tile of 64B rows (4 x 16B slots per row)
__device__ __forceinline__ uint32_t swz(int r, int c16) {
    return (uint32_t)(r * 64 + ((c16 ^ ((r >> 1) & 3)) << 4));
}

// ---------------------------------------------------------------------------
// HMMA bf16x3 GEMM:  C[M,N] = Ah@Bh^T + Ah@Bl^T + Al@Bh^T   (A,B K-major)
// CTA tile 128(M) x 64(N), 8 warps (warp tile 32x32), K-chunk 32, 3-stage
// cp.async pipeline.  Small SMEM (72KB) + low regs => 2 CTAs resident / SM
// (16 warps) so the tensor pipe stays fed across barriers / LDSM waits.
// ---------------------------------------------------------------------------
enum { MODE_F32 = 0, MODE_SPLIT = 1, MODE_SPLIT_T = 2 };

constexpr int A_TILE_B = 8192;    // 128 rows x 64B
constexpr int B_TILE_B = 4096;    // 64 rows x 64B
constexpr int STAGE_B = 2 * A_TILE_B + 2 * B_TILE_B;  // 24KB: Ah, Al, Bh, Bl
constexpr int OFF_AH = 0;
constexpr int OFF_AL = A_TILE_B;
constexpr int OFF_BH = 2 * A_TILE_B;
constexpr int OFF_BL = 2 * A_TILE_B + B_TILE_B;
constexpr int SMEM_SZ = 3 * STAGE_B;  // 72KB

__device__ __forceinline__ void cp_chunk(
    uint32_t sbase, int st, const __nv_bfloat16* A0, const __nv_bfloat16* A1,
    const __nv_bfloat16* B0, const __nv_bfloat16* B1, int lda, int ldb,
    int kk, int t) {
    const uint32_t stb = sbase + st * STAGE_B;
    // A tiles: 128 rows x 4 slots = 512 16B ops per tile; 2 per thread
#pragma unroll
    for (int i = 0; i < 2; i++) {
        int e = t + i * 256;
        int r = e >> 2, c16 = e & 3;
        uint32_t o = swz(r, c16);
        const char* ga = (const char*)(A0 + (size_t)r * lda + kk) + c16 * 16;
        const char* gb = (const char*)(A1 + (size_t)r * lda + kk) + c16 * 16;
        CP_ASYNC16(stb + OFF_AH + o, ga);
        CP_ASYNC16(stb + OFF_AL + o, gb);
    }
    // B tiles: 64 rows x 4 slots = 256 ops per tile; 1 per thread
    {
        int r = t >> 2, c16 = t & 3;
        uint32_t o = swz(r, c16);
        const char* ga = (const char*)(B0 + (size_t)r * ldb + kk) + c16 * 16;
        const char* gb = (const char*)(B1 + (size_t)r * ldb + kk) + c16 * 16;
        CP_ASYNC16(stb + OFF_BH + o, ga);
        CP_ASYNC16(stb + OFF_BL + o, gb);
    }
    CP_COMMIT();
}

template <int MODE>
__global__ void __launch_bounds__(256, 2)
gemm_hmma(const __nv_bfloat16* __restrict__ Ah, const __nv_bfloat16* __restrict__ Al,
          const __nv_bfloat16* __restrict__ Bh, const __nv_bfloat16* __restrict__ Bl,
          float* __restrict__ C, __nv_bfloat16* __restrict__ Ch,
          __nv_bfloat16* __restrict__ Cl, int Mtot, int Ntot, int K,
          int lda, int ldb, int azoff, int bzoff, long long czoff) {
    extern __shared__ char sm[];
    const uint32_t sbase = smem_u32(sm);
    const int t = threadIdx.x, lid = t & 31, wid = t >> 5;
    const int wm = wid & 3, wn = wid >> 2;           // 4 x 2 warp grid
    const int m0 = blockIdx.y * 128, n0 = blockIdx.x * 64;
    const size_t z = blockIdx.z;

    const __nv_bfloat16* A0 = Ah + (size_t)m0 * lda + z * azoff;
    const __nv_bfloat16* A1 = Al + (size_t)m0 * lda + z * azoff;
    const __nv_bfloat16* B0 = Bh + (size_t)n0 * ldb + z * bzoff;
    const __nv_bfloat16* B1 = Bl + (size_t)n0 * ldb + z * bzoff;
    C += z * czoff;

    float acc[2][4][4];
#pragma unroll
    for (int i = 0; i < 2; i++)
#pragma unroll
        for (int j = 0; j < 4; j++)
#pragma unroll
            for (int k = 0; k < 4; k++) acc[i][j][k] = 0.0f;

    const int NCH = K >> 5;  // 32-wide chunks

    // ldmatrix lane coords
    const int a_row = lid & 15;
    const int a_chi = lid >> 4;
    const int b_row = (lid & 7) + ((lid >> 4) << 3);
    const int b_chi = (lid >> 3) & 1;

    cp_chunk(sbase, 0, A0, A1, B0, B1, lda, ldb, 0, t);
    cp_chunk(sbase, 1, A0, A1, B0, B1, lda, ldb, 32, t);

    for (int c = 0; c < NCH; c++) {
        CP_WAIT1();
        __syncthreads();
        if (c + 2 < NCH)
            cp_chunk(sbase, (c + 2) % 3, A0, A1, B0, B1, lda, ldb, (c + 2) * 32, t);
        else
            CP_COMMIT();  // keep group count so WAIT1 drains chunk c+1

        const uint32_t base = sbase + (c % 3) * STAGE_B;
#pragma unroll
        for (int q = 0; q < 2; q++) {
            uint32_t ahf[2][4], alf[2][4], bhf[2][2], blf[2][2];
#pragma unroll
            for (int am = 0; am < 2; am++) {
                int r = wm * 32 + am * 16 + a_row;
                uint32_t off = swz(r, q * 2 + a_chi);
                ldsm4(ahf[am], base + OFF_AH + off);
                ldsm4(alf[am], base + OFF_AL + off);
            }
            {
                int r = wn * 32 + b_row;          // g2 = 0 -> n 0..15
                uint32_t off = swz(r, q * 2 + b_chi);
                uint32_t rh[4], rl[4];
                ldsm4(rh, base + OFF_BH + off);
                ldsm4(rl, base + OFF_BL + off);
                bhf[0][0] = rh[0]; bhf[0][1] = rh[1];
                bhf[1][0] = rh[2]; bhf[1][1] = rh[3];
                blf[0][0] = rl[0]; blf[0][1] = rl[1];
                blf[1][0] = rl[2]; blf[1][1] = rl[3];
            }
            uint32_t bhf2[2][2], blf2[2][2];
            {
                int r = wn * 32 + 16 + b_row;     // g2 = 1 -> n 16..31
                uint32_t off = swz(r, q * 2 + b_chi);
                uint32_t rh[4], rl[4];
                ldsm4(rh, base + OFF_BH + off);
                ldsm4(rl, base + OFF_BL + off);
                bhf2[0][0] = rh[0]; bhf2[0][1] = rh[1];
                bhf2[1][0] = rh[2]; bhf2[1][1] = rh[3];
                blf2[0][0] = rl[0]; blf2[0][1] = rl[1];
                blf2[1][0] = rl[2]; blf2[1][1] = rl[3];
            }
#pragma unroll
            for (int am = 0; am < 2; am++) {
                mma16816(acc[am][0], ahf[am], bhf[0]);
                mma16816(acc[am][1], ahf[am], bhf[1]);
                mma16816(acc[am][2], ahf[am], bhf2[0]);
                mma16816(acc[am][3], ahf[am], bhf2[1]);
            }
#pragma unroll
            for (int am = 0; am < 2; am++) {
                mma16816(acc[am][0], ahf[am], blf[0]);
                mma16816(acc[am][1], ahf[am], blf[1]);
                mma16816(acc[am][2], ahf[am], blf2[0]);
                mma16816(acc[am][3], ahf[am], blf2[1]);
            }
#pragma unroll
            for (int am = 0; am < 2; am++) {
                mma16816(acc[am][0], alf[am], bhf[0]);
                mma16816(acc[am][1], alf[am], bhf[1]);
                mma16816(acc[am][2], alf[am], bhf2[0]);
                mma16816(acc[am][3], alf[am], bhf2[1]);
            }
        }
    }

    // epilogue
    const int t4 = lid >> 2;
    const int n2 = (lid & 3) * 2;
#pragma unroll
    for (int am = 0; am < 2; am++) {
#pragma unroll
        for (int an = 0; an < 4; an++) {
            int m_lo = m0 + wm * 32 + am * 16 + t4;
            int n = n0 + wn * 32 + an * 8 + n2;
            float* a4 = acc[am][an];
            if (MODE == MODE_F32) {
                __stcs((float2*)(C + (size_t)m_lo * Ntot + n),
                       make_float2(a4[0], a4[1]));
                __stcs((float2*)(C + (size_t)(m_lo + 8) * Ntot + n),
                       make_float2(a4[2], a4[3]));
            } else if (MODE == MODE_SPLIT) {
#pragma unroll
                for (int h2 = 0; h2 < 2; h2++) {
                    int m = m_lo + 8 * h2;
                    float v0 = a4[2 * h2], v1 = a4[2 * h2 + 1];
                    __nv_bfloat16 h0 = __float2bfloat16(v0);
                    __nv_bfloat16 h1 = __float2bfloat16(v1);
                    __nv_bfloat162 hh; hh.x = h0; hh.y = h1;
                    __nv_bfloat162 ll;
                    ll.x = __float2bfloat16(v0 - __bfloat162float(h0));
                    ll.y = __float2bfloat16(v1 - __bfloat162float(h1));
                    *(__nv_bfloat162*)(Ch + (size_t)m * Ntot + n) = hh;
                    *(__nv_bfloat162*)(Cl + (size_t)m * Ntot + n) = ll;
                }
            } else {  // MODE_SPLIT_T
#pragma unroll
                for (int h2 = 0; h2 < 2; h2++) {
                    int m = m_lo + 8 * h2;
#pragma unroll
                    for (int e = 0; e < 2; e++) {
                        float v = a4[2 * h2 + e];
                        __nv_bfloat16 h = __float2bfloat16(v);
                        Ch[(size_t)(n + e) * Mtot + m] = h;
                        Cl[(size_t)(n + e) * Mtot + m] =
                            __float2bfloat16(v - __bfloat162float(h));
                    }
                }
            }
        }
    }
}

// ---------------------------------------------------------------------------
// splits
// ---------------------------------------------------------------------------
__global__ void split_x(const float* __restrict__ x, __nv_bfloat16* __restrict__ xh,
                        __nv_bfloat16* __restrict__ xl) {
    int i = blockIdx.x * 256 + threadIdx.x;
    float v = x[i];
    __nv_bfloat16 h = __float2bfloat16(v);
    xh[i] = h;
    xl[i] = __float2bfloat16(v - __bfloat162float(h));
}

struct W9 { const float* p[9]; };

// transpose + split all 9 weights; one launch, coalesced via shared tile
__global__ void splitT_all(W9 w9, __nv_bfloat16* __restrict__ WTc_h,
                           __nv_bfloat16* __restrict__ WTc_l,
                           __nv_bfloat16* __restrict__ WTv_h,
                           __nv_bfloat16* __restrict__ WTv_l) {
    __shared__ float tile[32][33];
    const int tx = threadIdx.x, ty = threadIdx.y;
    const int kt = blockIdx.x * 32, nt = blockIdx.y * 32;
    const int wi = blockIdx.z;
    const float* w = w9.p[wi];
#pragma unroll
    for (int j = 0; j < 4; j++) {
        int r = ty + 8 * j;
        tile[r][tx] = w[(size_t)(kt + r) * D + nt + tx];
    }
    __syncthreads();
#pragma unroll
    for (int j = 0; j < 4; j++) {
        int n_loc = ty + 8 * j;
        float v = tile[tx][n_loc];
        __nv_bfloat16 h = __float2bfloat16(v);
        __nv_bfloat16 l = __float2bfloat16(v - __bfloat162float(h));
        if (wi < 8) {
            size_t o = (size_t)(wi * 512 + nt + n_loc) * D + kt + tx;
            WTc_h[o] = h;
            WTc_l[o] = l;
        } else {
            size_t o = (size_t)(nt + n_loc) * D + kt + tx;
            WTv_h[o] = h;
            WTv_l[o] = l;
        }
    }
}

// ---------------------------------------------------------------------------
// warp-shuffle block helpers (256 threads, 8 warps)
// ---------------------------------------------------------------------------
__device__ __forceinline__ float wmax(float v) {
#pragma unroll
    for (int o = 16; o; o >>= 1) v = fmaxf(v, __shfl_xor_sync(0xffffffffu, v, o));
    return v;
}
__device__ __forceinline__ float blockMax8(float v, float* sw, int w, int l) {
    v = wmax(v);
    if (l == 0) sw[w] = v;
    __syncthreads();
    float r = sw[0];
#pragma unroll
    for (int k = 1; k < 8; k++) r = fmaxf(r, sw[k]);
    __syncthreads();
    return r;
}
__device__ __forceinline__ float blockSum8(float v, float* sw, int w, int l) {
#pragma unroll
    for (int o = 16; o; o >>= 1) v += __shfl_xor_sync(0xffffffffu, v, o);
    if (l == 0) sw[w] = v;
    __syncthreads();
    float r = 0.0f;
#pragma unroll
    for (int k = 0; k < 8; k++) r += sw[k];
    __syncthreads();
    return r;
}
// returns EXCLUSIVE prefix of s across the block; *tot = block total
__device__ __forceinline__ float blockScanExcl(float s, float* sw, int w, int l,
                                               float* tot) {
    float incl = s;
#pragma unroll
    for (int o = 1; o < 32; o <<= 1) {
        float x = __shfl_up_sync(0xffffffffu, incl, o);
        if (l >= o) incl += x;
    }
    if (l == 31) sw[w] = incl;
    __syncthreads();
    float woff = 0.0f, tt = 0.0f;
#pragma unroll
    for (int k = 0; k < 8; k++) {
        float sv = sw[k];
        tt += sv;
        if (k < w) woff += sv;
    }
    __syncthreads();
    *tot = tt;
    return incl - s + woff;
}

// ---------------------------------------------------------------------------
// Fused per-row pipeline (also emits bf16 hi/lo of att_weight)
// ---------------------------------------------------------------------------
__global__ __launch_bounds__(256) void row_fused(float* __restrict__ Wout) {
    __shared__ float sw[8];
    const int i = blockIdx.x;
    const int t = threadIdx.x;
    const int w = t >> 5, l = t & 31;
    const int j0 = t * 16;
    const float inv_norm = 0.04419417382415922f;  // 1/sqrt(512)

    const float* Sl = g_S4 + 0 * (size_t)S * S + (size_t)i * S;
    const float* Sr = g_S4 + 1 * (size_t)S * S + (size_t)i * S;
    const float* Sg = g_S4 + 2 * (size_t)S * S + (size_t)i * S;
    const float* Sp = g_S4 + 3 * (size_t)S * S + (size_t)i * S;

    float lcdf[16], rcdf[16];

    {  // left boundary
        float e[16];
        float m = -1e30f;
#pragma unroll
        for (int u4 = 0; u4 < 4; u4++) {
            float4 v = __ldcs(reinterpret_cast<const float4*>(Sl + j0 + 4 * u4));
            e[4 * u4 + 0] = v.x; e[4 * u4 + 1] = v.y;
            e[4 * u4 + 2] = v.z; e[4 * u4 + 3] = v.w;
        }
#pragma unroll
        for (int u = 0; u < 16; u++) {
            int j = j0 + u;
            float s = (j <= i) ? e[u] * inv_norm : -1e30f;
            e[u] = s;
            m = fmaxf(m, s);
        }
        m = blockMax8(m, sw, w, l);
        float lsum = 0.0f;
#pragma unroll
        for (int u = 0; u < 16; u++) {
            int j = j0 + u;
            float ev = (j <= i) ? __expf(e[u] - m) : 0.0f;
            e[u] = ev;
            lsum += ev;
        }
        float tot;
        float off = blockScanExcl(lsum, sw, w, l, &tot);
        float inv = 1.0f / tot;
        float c = 0.0f;
#pragma unroll
        for (int u = 0; u < 16; u++) {
            c += e[u];
            lcdf[u] = (c + off) * inv;
        }
    }

    {  // right boundary
        float e[16];
        float m = -1e30f;
#pragma unroll
        for (int u4 = 0; u4 < 4; u4++) {
            float4 v = __ldcs(reinterpret_cast<const float4*>(Sr + j0 + 4 * u4));
            e[4 * u4 + 0] = v.x; e[4 * u4 + 1] = v.y;
            e[4 * u4 + 2] = v.z; e[4 * u4 + 3] = v.w;
        }
#pragma unroll
        for (int u = 0; u < 16; u++) {
            int j = j0 + u;
            float s = (j >= i) ? e[u] * inv_norm : -1e30f;
            e[u] = s;
            m = fmaxf(m, s);
        }
        m = blockMax8(m, sw, w, l);
        float rsum = 0.0f;
#pragma unroll
        for (int u = 0; u < 16; u++) {
            int j = j0 + u;
            float ev = (j >= i) ? __expf(e[u] - m) : 0.0f;
            e[u] = ev;
            rsum += ev;
        }
        float tot;
        float excl = blockScanExcl(rsum, sw, w, l, &tot);
        float suff = tot - excl - rsum;
        float inv = 1.0f / tot;
        float c = 0.0f;
#pragma unroll
        for (int u = 15; u >= 0; u--) {
            c += e[u];
            rcdf[u] = (c + suff) * inv;
        }
    }

    {  // combine + final softmax
        float wv[16], p[16];
#pragma unroll
        for (int u4 = 0; u4 < 4; u4++) {
            float4 vg = __ldcs(reinterpret_cast<const float4*>(Sg + j0 + 4 * u4));
            float4 vp = __ldcs(reinterpret_cast<const float4*>(Sp + j0 + 4 * u4));
            wv[4 * u4 + 0] = vg.x; wv[4 * u4 + 1] = vg.y;
            wv[4 * u4 + 2] = vg.z; wv[4 * u4 + 3] = vg.w;
            p[4 * u4 + 0] = vp.x; p[4 * u4 + 1] = vp.y;
            p[4 * u4 + 2] = vp.z; p[4 * u4 + 3] = vp.w;
        }
        float m = -1e30f;
#pragma unroll
        for (int u = 0; u < 16; u++) {
            float sc = (wv[u] + p[u] * lcdf[u] * rcdf[u]) * inv_norm;
            wv[u] = sc;
            m = fmaxf(m, sc);
        }
        m = blockMax8(m, sw, w, l);
        float lsum = 0.0f;
#pragma unroll
        for (int u = 0; u < 16; u++) {
            float ev = __expf(wv[u] - m);
            wv[u] = ev;
            lsum += ev;
        }
        float tot = blockSum8(lsum, sw, w, l);
        float inv = 1.0f / tot;
        float* Wrow = Wout + (size_t)i * S + j0;
        __nv_bfloat16* Hrow = g_Wh + (size_t)i * S + j0;
        __nv_bfloat16* Lrow = g_Wl + (size_t)i * S + j0;
#pragma unroll
        for (int u4 = 0; u4 < 4; u4++) {
            float4 o;
            o.x = wv[4 * u4 + 0] * inv;
            o.y = wv[4 * u4 + 1] * inv;
            o.z = wv[4 * u4 + 2] * inv;
            o.w = wv[4 * u4 + 3] * inv;
            *reinterpret_cast<float4*>(Wrow + 4 * u4) = o;
            float vv[4] = {o.x, o.y, o.z, o.w};
#pragma unroll
            for (int u = 0; u < 4; u++) {
                __nv_bfloat16 h = __float2bfloat16(vv[u]);
                Hrow[4 * u4 + u] = h;
                Lrow[4 * u4 + u] = __float2bfloat16(vv[u] - __bfloat162float(h));
            }
        }
    }
}

// ---------------------------------------------------------------------------
// Launch. inputs: x, w_ql, w_kl, w_qr, w_kr, w_qg, w_kg, w_qloc, w_kloc, w_v
// Output layout: [att_output (S*D) | att_weight (S*S)]
// ---------------------------------------------------------------------------
extern "C" void kernel_launch(void* const* d_in, const int* in_sizes, int n_in,
                              void* d_out, int out_size) {
    const float* x = (const float*)d_in[0];
    W9 w9;
    for (int i = 0; i < 9; i++) w9.p[i] = (const float*)d_in[1 + i];

    float* out = (float*)d_out;
    float* Wout = out + SD;

    __nv_bfloat16 *Xh, *Xl, *WTc_h, *WTc_l, *WTv_h, *WTv_l;
    __nv_bfloat16 *Pc_h, *Pc_l, *VTh, *VTl, *Wh, *Wl;
    float* S4;
    cudaGetSymbolAddress((void**)&Xh, g_Xh);
    cudaGetSymbolAddress((void**)&Xl, g_Xl);
    cudaGetSymbolAddress((void**)&WTc_h, g_WTc_h);
    cudaGetSymbolAddress((void**)&WTc_l, g_WTc_l);
    cudaGetSymbolAddress((void**)&WTv_h, g_WTv_h);
    cudaGetSymbolAddress((void**)&WTv_l, g_WTv_l);
    cudaGetSymbolAddress((void**)&Pc_h, g_Pc_h);
    cudaGetSymbolAddress((void**)&Pc_l, g_Pc_l);
    cudaGetSymbolAddress((void**)&VTh, g_VTh);
    cudaGetSymbolAddress((void**)&VTl, g_VTl);
    cudaGetSymbolAddress((void**)&S4, g_S4);
    cudaGetSymbolAddress((void**)&Wh, g_Wh);
    cudaGetSymbolAddress((void**)&Wl, g_Wl);

    cudaFuncSetAttribute(gemm_hmma<MODE_F32>,
                         cudaFuncAttributeMaxDynamicSharedMemorySize, SMEM_SZ);
    cudaFuncSetAttribute(gemm_hmma<MODE_SPLIT>,
                         cudaFuncAttributeMaxDynamicSharedMemorySize, SMEM_SZ);
    cudaFuncSetAttribute(gemm_hmma<MODE_SPLIT_T>,
                         cudaFuncAttributeMaxDynamicSharedMemorySize, SMEM_SZ);

    // 1) splits: x elementwise, weights transposed (one launch each)
    split_x<<<SD / 256, 256>>>(x, Xh, Xl);
    dim3 tb(32, 8);
    dim3 tg(D / 32, D / 32, 9);
    splitT_all<<<tg, tb>>>(w9, WTc_h, WTc_l, WTv_h, WTv_l);

    // 2) fused projections: Pcat[4096, 4096] = x @ [w_ql|w_kl|...|w_kloc]
    dim3 gp(PCN / 64, S / 128, 1);
    gemm_hmma<MODE_SPLIT><<<gp, 256, SMEM_SZ>>>(
        Xh, Xl, WTc_h, WTc_l, nullptr, Pc_h, Pc_l,
        S, PCN, D, D, D, 0, 0, 0);

    //    v projection, written transposed: VT[512, 4096]
    dim3 gv(D / 64, S / 128, 1);
    gemm_hmma<MODE_SPLIT_T><<<gv, 256, SMEM_SZ>>>(
        Xh, Xl, WTv_h, WTv_l, nullptr, VTh, VTl,
        S, D, D, D, D, 0, 0, 0);

    // 3) four S x S score matrices in ONE batched launch (z = 0..3)
    dim3 gs(S / 64, S / 128, 4);
    gemm_hmma<MODE_F32><<<gs, 256, SMEM_SZ>>>(
        Pc_h, Pc_l, Pc_h + 512, Pc_l + 512, S4, nullptr, nullptr,
        S, S, D, PCN, PCN, 1024, 1024, (long long)S * S);

    // 4) fused boundary softmaxes + cumsums + combine + final softmax
    row_fused<<<S, 256>>>(Wout);

    // 5) att_output = att_weight @ v   (W bf16x3  x  V^T bf16x3)
    dim3 gf(D / 64, S / 128, 1);
    gemm_hmma<MODE_F32><<<gf, 256, SMEM_SZ>>>(
        Wh, Wl, VTh, VTl, out, nullptr, nullptr,
        S, D, S, S, S, 0, 0, 0);
}